// round 1
// baseline (speedup 1.0000x reference)
#include <cuda_runtime.h>
#include <cstdint>
#include <cstddef>

#define NMAX 200000
#define EMAX 600000
#define CH 128

// ---------------- scratch (device globals; no allocation allowed) ----------------
__device__ float g_h[(size_t)NMAX * CH];
__device__ float g_agg[(size_t)NMAX * CH];
__device__ float g_z[(size_t)NMAX * CH];
__device__ int   g_src[EMAX];
__device__ int   g_dst[EMAX];
__device__ int   g_idx64;

// ---------------- edge_index dtype sniffer ----------------
// If the data is int64 (little-endian), every odd 32-bit word is a high word == 0
// (indices < 2^31). If int32, odd words are random node indices. OR a sample.
__global__ void detect_idx_kernel(const unsigned* __restrict__ p, int nwords)
{
    __shared__ unsigned s[32];
    unsigned v = 0;
    for (int i = threadIdx.x; i < 4096; i += blockDim.x) {
        int w = 2 * i + 1;
        if (w < nwords) v |= p[w];
    }
#pragma unroll
    for (int o = 16; o > 0; o >>= 1) v |= __shfl_xor_sync(0xffffffffu, v, o);
    int lane = threadIdx.x & 31, wid = threadIdx.x >> 5;
    if (lane == 0) s[wid] = v;
    __syncthreads();
    if (threadIdx.x == 0) {
        unsigned r = 0;
        int nw = (blockDim.x + 31) >> 5;
        for (int i = 0; i < nw; i++) r |= s[i];
        g_idx64 = (r == 0) ? 1 : 0;
    }
}

__global__ void convert_idx_kernel(const void* __restrict__ ei, int E)
{
    int i = blockIdx.x * blockDim.x + threadIdx.x;
    if (i >= E) return;
    if (g_idx64) {
        const long long* p = (const long long*)ei;
        g_src[i] = (int)p[i];
        g_dst[i] = (int)p[(size_t)E + i];
    } else {
        const int* p = (const int*)ei;
        g_src[i] = p[i];
        g_dst[i] = p[E + i];
    }
}

// ---------------- zero fill ----------------
__global__ void zero_kernel(float4* __restrict__ p, int n4)
{
    int i = blockIdx.x * blockDim.x + threadIdx.x;
    int stride = gridDim.x * blockDim.x;
    float4 z = make_float4(0.f, 0.f, 0.f, 0.f);
    for (; i < n4; i += stride) p[i] = z;
}

// ---------------- fused edge-GEMM + message + scatter-add ----------------
// One edge per warp. lane l owns channels [4l, 4l+4).
// msg = relu(h[src] + edge_attr[e] @ We + be); agg[dst] += msg (vector red).
__global__ __launch_bounds__(256)
void msg_scatter(const float* __restrict__ h, const float* __restrict__ eattr,
                 const float* __restrict__ We, const float* __restrict__ be,
                 float* __restrict__ agg, int E)
{
    __shared__ float4 Wes[16][32];   // [k][c4] : We row-major [16][128]
    __shared__ float4 bes[32];
    int tid = threadIdx.x;
    for (int i = tid; i < 16 * 32; i += 256)
        ((float4*)Wes)[i] = ((const float4*)We)[i];
    if (tid < 32) bes[tid] = ((const float4*)be)[tid];
    __syncthreads();

    int lane = tid & 31;
    int gw = (blockIdx.x * 256 + tid) >> 5;
    int nw = (gridDim.x * 256) >> 5;

    for (int e = gw; e < E; e += nw) {
        int s = g_src[e];
        int d = g_dst[e];
        const float4* ea = ((const float4*)eattr) + (size_t)e * 4;
        float4 e0 = __ldg(ea + 0), e1 = __ldg(ea + 1);
        float4 e2 = __ldg(ea + 2), e3 = __ldg(ea + 3);
        float ev[16] = {e0.x, e0.y, e0.z, e0.w, e1.x, e1.y, e1.z, e1.w,
                        e2.x, e2.y, e2.z, e2.w, e3.x, e3.y, e3.z, e3.w};
        float4 acc = bes[lane];
#pragma unroll
        for (int k = 0; k < 16; k++) {
            float4 w = Wes[k][lane];
            acc.x += ev[k] * w.x;
            acc.y += ev[k] * w.y;
            acc.z += ev[k] * w.z;
            acc.w += ev[k] * w.w;
        }
        float4 hv = *(const float4*)(h + (size_t)s * CH + lane * 4);
        float mx = fmaxf(hv.x + acc.x, 0.f);
        float my = fmaxf(hv.y + acc.y, 0.f);
        float mz = fmaxf(hv.z + acc.z, 0.f);
        float mw = fmaxf(hv.w + acc.w, 0.f);
        size_t gaddr = __cvta_generic_to_global(agg + (size_t)d * CH + lane * 4);
        asm volatile("red.global.add.v4.f32 [%0], {%1,%2,%3,%4};"
                     :: "l"(gaddr), "f"(mx), "f"(my), "f"(mz), "f"(mw)
                     : "memory");
    }
}

// ---------------- GEMM + bias + ReLU ----------------
// out[M,128] = relu( in @ W[128,128] + b ), where in = FUSE ? (1+eps)*A + B2 : A.
// Whole W staged in smem (64 KB) + 64-row A tile (32 KB). One __syncthreads.
// Thread tile: 4 rows x 8 cols (cols split n0a=nx*4 and n0b=64+nx*4 -> conflict-free LDS.128).
template <bool FUSE>
__global__ __launch_bounds__(256)
void gemm_relu(const float* __restrict__ A, const float* __restrict__ B2,
               const float* __restrict__ epsp,
               const float* __restrict__ W, const float* __restrict__ bias,
               float* __restrict__ out, int M)
{
    extern __shared__ float sm[];
    float* Ws = sm;              // 128*128
    float* As = sm + 128 * 128;  // 64*128, row-major [r][k]
    const int tid = threadIdx.x;

#pragma unroll
    for (int i = 0; i < 16; i++) {
        int idx = tid + i * 256;  // float4 index 0..4095
        ((float4*)Ws)[idx] = ((const float4*)W)[idx];
    }

    float epc = 1.0f;
    if (FUSE) epc = 1.0f + __ldg(epsp);

    const int row0 = blockIdx.x * 64;
#pragma unroll
    for (int i = 0; i < 8; i++) {
        int idx = tid + i * 256;  // float4 index 0..2047
        int r = idx >> 5;
        int kc = idx & 31;
        int g = row0 + r;
        float4 v = make_float4(0.f, 0.f, 0.f, 0.f);
        if (g < M) {
            v = ((const float4*)(A + (size_t)g * CH))[kc];
            if (FUSE) {
                float4 b = ((const float4*)(B2 + (size_t)g * CH))[kc];
                v.x = epc * v.x + b.x;
                v.y = epc * v.y + b.y;
                v.z = epc * v.z + b.z;
                v.w = epc * v.w + b.w;
            }
        }
        ((float4*)(As + r * CH))[kc] = v;
    }
    __syncthreads();

    const int nx = tid & 15;
    const int ry = tid >> 4;
    const int r0 = ry * 4;
    const int n0a = nx * 4;
    const int n0b = 64 + nx * 4;

    float acc[4][8];
#pragma unroll
    for (int j = 0; j < 4; j++)
#pragma unroll
        for (int i = 0; i < 8; i++) acc[j][i] = 0.f;

    const float* As0 = As + r0 * CH;
#pragma unroll 8
    for (int k = 0; k < CH; ++k) {
        float4 b0 = *(const float4*)(Ws + k * CH + n0a);
        float4 b1 = *(const float4*)(Ws + k * CH + n0b);
        float a[4];
        a[0] = As0[k];
        a[1] = As0[CH + k];
        a[2] = As0[2 * CH + k];
        a[3] = As0[3 * CH + k];
#pragma unroll
        for (int j = 0; j < 4; j++) {
            acc[j][0] += a[j] * b0.x;
            acc[j][1] += a[j] * b0.y;
            acc[j][2] += a[j] * b0.z;
            acc[j][3] += a[j] * b0.w;
            acc[j][4] += a[j] * b1.x;
            acc[j][5] += a[j] * b1.y;
            acc[j][6] += a[j] * b1.z;
            acc[j][7] += a[j] * b1.w;
        }
    }

    float4 ba = __ldg((const float4*)(bias + n0a));
    float4 bb = __ldg((const float4*)(bias + n0b));
#pragma unroll
    for (int j = 0; j < 4; j++) {
        int g = row0 + r0 + j;
        if (g < M) {
            float4 o;
            o.x = fmaxf(acc[j][0] + ba.x, 0.f);
            o.y = fmaxf(acc[j][1] + ba.y, 0.f);
            o.z = fmaxf(acc[j][2] + ba.z, 0.f);
            o.w = fmaxf(acc[j][3] + ba.w, 0.f);
            *(float4*)(out + (size_t)g * CH + n0a) = o;
            o.x = fmaxf(acc[j][4] + bb.x, 0.f);
            o.y = fmaxf(acc[j][5] + bb.y, 0.f);
            o.z = fmaxf(acc[j][6] + bb.z, 0.f);
            o.w = fmaxf(acc[j][7] + bb.w, 0.f);
            *(float4*)(out + (size_t)g * CH + n0b) = o;
        }
    }
}

// ---------------- launch ----------------
extern "C" void kernel_launch(void* const* d_in, const int* in_sizes, int n_in,
                              void* d_out, int out_size)
{
    const float* x     = (const float*)d_in[0];
    const void*  eidx  = d_in[1];
    const float* eattr = (const float*)d_in[2];
    const float* W_enc = (const float*)d_in[3];
    const float* b_enc = (const float*)d_in[4];
    const float* We1   = (const float*)d_in[5];
    const float* be1   = (const float*)d_in[6];
    const float* W11   = (const float*)d_in[7];
    const float* b11   = (const float*)d_in[8];
    const float* W12   = (const float*)d_in[9];
    const float* b12   = (const float*)d_in[10];
    const float* eps1  = (const float*)d_in[11];
    const float* We2   = (const float*)d_in[12];
    const float* be2   = (const float*)d_in[13];
    const float* W21   = (const float*)d_in[14];
    const float* b21   = (const float*)d_in[15];
    const float* W22   = (const float*)d_in[16];
    const float* b22   = (const float*)d_in[17];
    const float* eps2  = (const float*)d_in[18];

    const int N = in_sizes[0] / CH;
    const int E = in_sizes[2] / 16;
    float* out = (float*)d_out;

    float *hP, *aggP, *zP;
    cudaGetSymbolAddress((void**)&hP, g_h);
    cudaGetSymbolAddress((void**)&aggP, g_agg);
    cudaGetSymbolAddress((void**)&zP, g_z);

    const int SMEM = (128 * 128 + 64 * 128) * (int)sizeof(float);  // 96 KB
    cudaFuncSetAttribute((const void*)gemm_relu<false>,
                         cudaFuncAttributeMaxDynamicSharedMemorySize, SMEM);
    cudaFuncSetAttribute((const void*)gemm_relu<true>,
                         cudaFuncAttributeMaxDynamicSharedMemorySize, SMEM);

    // index decode (dtype sniff + convert to int32 src/dst)
    detect_idx_kernel<<<1, 256>>>((const unsigned*)eidx, 2 * E);
    convert_idx_kernel<<<(E + 255) / 256, 256>>>(eidx, E);

    const int gb = (N + 63) / 64;

    // encoder: h = relu(x @ W_enc + b_enc)
    gemm_relu<false><<<gb, 256, SMEM>>>(x, nullptr, nullptr, W_enc, b_enc, hP, N);

    // ---- conv1 ----
    zero_kernel<<<1184, 256>>>((float4*)aggP, N * CH / 4);
    msg_scatter<<<2368, 256>>>(hP, eattr, We1, be1, aggP, E);
    gemm_relu<true><<<gb, 256, SMEM>>>(hP, aggP, eps1, W11, b11, zP, N);
    gemm_relu<false><<<gb, 256, SMEM>>>(zP, nullptr, nullptr, W12, b12, hP, N);

    // ---- conv2 ----
    zero_kernel<<<1184, 256>>>((float4*)aggP, N * CH / 4);
    msg_scatter<<<2368, 256>>>(hP, eattr, We2, be2, aggP, E);
    gemm_relu<true><<<gb, 256, SMEM>>>(hP, aggP, eps2, W21, b21, zP, N);
    gemm_relu<false><<<gb, 256, SMEM>>>(zP, nullptr, nullptr, W22, b22, out, N);
}

// round 2
// speedup vs baseline: 1.3331x; 1.3331x over previous
#include <cuda_runtime.h>
#include <cuda_bf16.h>
#include <cstdint>
#include <cstddef>

#define NMAX 200000
#define EMAX 600000
#define CH 128

// ---------------- scratch (device globals; no allocation allowed) ----------------
__device__ float g_h[(size_t)NMAX * CH];
__device__ float g_agg[(size_t)NMAX * CH];
__device__ float g_z[(size_t)NMAX * CH];
__device__ int   g_src[EMAX];
__device__ int   g_dst[EMAX];
__device__ int   g_idx64;

// ---------------- edge_index dtype sniffer ----------------
__global__ void detect_idx_kernel(const unsigned* __restrict__ p, int nwords)
{
    __shared__ unsigned s[32];
    unsigned v = 0;
    for (int i = threadIdx.x; i < 4096; i += blockDim.x) {
        int w = 2 * i + 1;
        if (w < nwords) v |= p[w];
    }
#pragma unroll
    for (int o = 16; o > 0; o >>= 1) v |= __shfl_xor_sync(0xffffffffu, v, o);
    int lane = threadIdx.x & 31, wid = threadIdx.x >> 5;
    if (lane == 0) s[wid] = v;
    __syncthreads();
    if (threadIdx.x == 0) {
        unsigned r = 0;
        int nw = (blockDim.x + 31) >> 5;
        for (int i = 0; i < nw; i++) r |= s[i];
        g_idx64 = (r == 0) ? 1 : 0;
    }
}

__global__ void convert_idx_kernel(const void* __restrict__ ei, int E)
{
    int i = blockIdx.x * blockDim.x + threadIdx.x;
    if (i >= E) return;
    if (g_idx64) {
        const long long* p = (const long long*)ei;
        g_src[i] = (int)p[i];
        g_dst[i] = (int)p[(size_t)E + i];
    } else {
        const int* p = (const int*)ei;
        g_src[i] = p[i];
        g_dst[i] = p[E + i];
    }
}

// ---------------- zero fill ----------------
__global__ void zero_kernel(float4* __restrict__ p, int n4)
{
    int i = blockIdx.x * blockDim.x + threadIdx.x;
    int stride = gridDim.x * blockDim.x;
    float4 z = make_float4(0.f, 0.f, 0.f, 0.f);
    for (; i < n4; i += stride) p[i] = z;
}

// ---------------- fused edge-GEMM + message + scatter-add ----------------
__global__ __launch_bounds__(256)
void msg_scatter(const float* __restrict__ h, const float* __restrict__ eattr,
                 const float* __restrict__ We, const float* __restrict__ be,
                 float* __restrict__ agg, int E)
{
    __shared__ float4 Wes[16][32];
    __shared__ float4 bes[32];
    int tid = threadIdx.x;
    for (int i = tid; i < 16 * 32; i += 256)
        ((float4*)Wes)[i] = ((const float4*)We)[i];
    if (tid < 32) bes[tid] = ((const float4*)be)[tid];
    __syncthreads();

    int lane = tid & 31;
    int gw = (blockIdx.x * 256 + tid) >> 5;
    int nw = (gridDim.x * 256) >> 5;

    for (int e = gw; e < E; e += nw) {
        int s = g_src[e];
        int d = g_dst[e];
        const float4* ea = ((const float4*)eattr) + (size_t)e * 4;
        float4 e0 = __ldg(ea + 0), e1 = __ldg(ea + 1);
        float4 e2 = __ldg(ea + 2), e3 = __ldg(ea + 3);
        float ev[16] = {e0.x, e0.y, e0.z, e0.w, e1.x, e1.y, e1.z, e1.w,
                        e2.x, e2.y, e2.z, e2.w, e3.x, e3.y, e3.z, e3.w};
        float4 acc = bes[lane];
#pragma unroll
        for (int k = 0; k < 16; k++) {
            float4 w = Wes[k][lane];
            acc.x += ev[k] * w.x;
            acc.y += ev[k] * w.y;
            acc.z += ev[k] * w.z;
            acc.w += ev[k] * w.w;
        }
        float4 hv = *(const float4*)(h + (size_t)s * CH + lane * 4);
        float mx = fmaxf(hv.x + acc.x, 0.f);
        float my = fmaxf(hv.y + acc.y, 0.f);
        float mz = fmaxf(hv.z + acc.z, 0.f);
        float mw = fmaxf(hv.w + acc.w, 0.f);
        size_t gaddr = __cvta_generic_to_global(agg + (size_t)d * CH + lane * 4);
        asm volatile("red.global.add.v4.f32 [%0], {%1,%2,%3,%4};"
                     :: "l"(gaddr), "f"(mx), "f"(my), "f"(mz), "f"(mw)
                     : "memory");
    }
}

// ---------------- tensor-core GEMM + bias + ReLU (split-bf16, 3-term) ----------------
// out[M,128] = relu( in @ W[128,128] + b ), in = FUSE ? (1+eps)*A + B2 : A
// A,W split as v = hi + lo (bf16 each); C = Ah*Wh + Al*Wh + Ah*Wl (lo*lo dropped, ~2^-18 rel).
// CTA: 128 rows, 256 threads (8 warps), warp w -> rows [w*16, w*16+16), all 128 cols.
// smem: Ah/Al[128][136] bf16, Bh/Bl[128][136] bf16 (pad 8 -> conflict-free ldmatrix), bias[128].

#define LDP 136  // padded row length in bf16 elems

__device__ __forceinline__ void split_bf16(float v, __nv_bfloat16& h, __nv_bfloat16& l)
{
    h = __float2bfloat16(v);
    l = __float2bfloat16(v - __bfloat162float(h));
}

__device__ __forceinline__ void ldsm_x4(uint32_t& r0, uint32_t& r1, uint32_t& r2, uint32_t& r3,
                                        const void* p)
{
    uint32_t a = (uint32_t)__cvta_generic_to_shared(p);
    asm volatile("ldmatrix.sync.aligned.m8n8.x4.shared.b16 {%0,%1,%2,%3}, [%4];"
                 : "=r"(r0), "=r"(r1), "=r"(r2), "=r"(r3) : "r"(a));
}

__device__ __forceinline__ void ldsm_x4_t(uint32_t& r0, uint32_t& r1, uint32_t& r2, uint32_t& r3,
                                          const void* p)
{
    uint32_t a = (uint32_t)__cvta_generic_to_shared(p);
    asm volatile("ldmatrix.sync.aligned.m8n8.x4.trans.shared.b16 {%0,%1,%2,%3}, [%4];"
                 : "=r"(r0), "=r"(r1), "=r"(r2), "=r"(r3) : "r"(a));
}

__device__ __forceinline__ void mma_bf16(float* c, const uint32_t* a, uint32_t b0, uint32_t b1)
{
    asm volatile("mma.sync.aligned.m16n8k16.row.col.f32.bf16.bf16.f32 "
                 "{%0,%1,%2,%3}, {%4,%5,%6,%7}, {%8,%9}, {%0,%1,%2,%3};"
                 : "+f"(c[0]), "+f"(c[1]), "+f"(c[2]), "+f"(c[3])
                 : "r"(a[0]), "r"(a[1]), "r"(a[2]), "r"(a[3]), "r"(b0), "r"(b1));
}

template <bool FUSE>
__global__ __launch_bounds__(256)
void gemm_tc(const float* __restrict__ A, const float* __restrict__ B2,
             const float* __restrict__ epsp,
             const float* __restrict__ W, const float* __restrict__ bias,
             float* __restrict__ out, int M)
{
    extern __shared__ char smraw[];
    __nv_bfloat16* Ah = (__nv_bfloat16*)smraw;             // 128*136
    __nv_bfloat16* Al = Ah + 128 * LDP;
    __nv_bfloat16* Bh = Al + 128 * LDP;
    __nv_bfloat16* Bl = Bh + 128 * LDP;
    float* sbias = (float*)(Bl + 128 * LDP);

    const int tid = threadIdx.x;
    const int row0 = blockIdx.x * 128;

    if (tid < 128) sbias[tid] = __ldg(bias + tid);

    // stage W (hi/lo split)
#pragma unroll
    for (int i = 0; i < 16; i++) {
        int idx = tid + i * 256;       // float4 idx 0..4095
        int k = idx >> 5, c4 = idx & 31;
        float4 v = ((const float4*)W)[idx];
        __nv_bfloat16 h0, l0;
        split_bf16(v.x, h0, l0); Bh[k * LDP + c4 * 4 + 0] = h0; Bl[k * LDP + c4 * 4 + 0] = l0;
        split_bf16(v.y, h0, l0); Bh[k * LDP + c4 * 4 + 1] = h0; Bl[k * LDP + c4 * 4 + 1] = l0;
        split_bf16(v.z, h0, l0); Bh[k * LDP + c4 * 4 + 2] = h0; Bl[k * LDP + c4 * 4 + 2] = l0;
        split_bf16(v.w, h0, l0); Bh[k * LDP + c4 * 4 + 3] = h0; Bl[k * LDP + c4 * 4 + 3] = l0;
    }

    float epc = 1.0f;
    if (FUSE) epc = 1.0f + __ldg(epsp);

    // stage A tile (fused transform + hi/lo split)
#pragma unroll
    for (int i = 0; i < 16; i++) {
        int idx = tid + i * 256;       // float4 idx 0..4095
        int r = idx >> 5, c4 = idx & 31;
        int g = row0 + r;
        float4 v = make_float4(0.f, 0.f, 0.f, 0.f);
        if (g < M) {
            v = ((const float4*)(A + (size_t)g * CH))[c4];
            if (FUSE) {
                float4 b = ((const float4*)(B2 + (size_t)g * CH))[c4];
                v.x = epc * v.x + b.x;
                v.y = epc * v.y + b.y;
                v.z = epc * v.z + b.z;
                v.w = epc * v.w + b.w;
            }
        }
        __nv_bfloat16 h0, l0;
        split_bf16(v.x, h0, l0); Ah[r * LDP + c4 * 4 + 0] = h0; Al[r * LDP + c4 * 4 + 0] = l0;
        split_bf16(v.y, h0, l0); Ah[r * LDP + c4 * 4 + 1] = h0; Al[r * LDP + c4 * 4 + 1] = l0;
        split_bf16(v.z, h0, l0); Ah[r * LDP + c4 * 4 + 2] = h0; Al[r * LDP + c4 * 4 + 2] = l0;
        split_bf16(v.w, h0, l0); Ah[r * LDP + c4 * 4 + 3] = h0; Al[r * LDP + c4 * 4 + 3] = l0;
    }
    __syncthreads();

    const int warp = tid >> 5;
    const int lane = tid & 31;
    const int m0 = warp * 16;

    float acc[16][4];
#pragma unroll
    for (int t = 0; t < 16; t++)
#pragma unroll
        for (int j = 0; j < 4; j++) acc[t][j] = 0.f;

    const int arow = m0 + (lane & 15);
    const int aoff = ((lane >> 4) << 3);

#pragma unroll
    for (int kc = 0; kc < 8; kc++) {
        const int kb = kc * 16;
        uint32_t ah[4], al[4];
        ldsm_x4(ah[0], ah[1], ah[2], ah[3], Ah + arow * LDP + kb + aoff);
        ldsm_x4(al[0], al[1], al[2], al[3], Al + arow * LDP + kb + aoff);
        const int brow = kb + (lane & 15);
#pragma unroll
        for (int ng = 0; ng < 8; ng++) {
            const int n0 = ng * 16;
            uint32_t bh[4], bl[4];
            ldsm_x4_t(bh[0], bh[1], bh[2], bh[3], Bh + brow * LDP + n0 + aoff);
            ldsm_x4_t(bl[0], bl[1], bl[2], bl[3], Bl + brow * LDP + n0 + aoff);
            float* c0 = acc[ng * 2];
            float* c1 = acc[ng * 2 + 1];
            mma_bf16(c0, ah, bh[0], bh[1]);
            mma_bf16(c0, al, bh[0], bh[1]);
            mma_bf16(c0, ah, bl[0], bl[1]);
            mma_bf16(c1, ah, bh[2], bh[3]);
            mma_bf16(c1, al, bh[2], bh[3]);
            mma_bf16(c1, ah, bl[2], bl[3]);
        }
    }

    // epilogue: bias + relu + store (thread owns rows r, r+8; cols nt*8 + (lane&3)*2)
    const int r = row0 + m0 + (lane >> 2);
    const int cb = (lane & 3) * 2;
#pragma unroll
    for (int t = 0; t < 16; t++) {
        const int n = t * 8 + cb;
        const float b0 = sbias[n], b1 = sbias[n + 1];
        if (r < M) {
            float2 o;
            o.x = fmaxf(acc[t][0] + b0, 0.f);
            o.y = fmaxf(acc[t][1] + b1, 0.f);
            *(float2*)(out + (size_t)r * CH + n) = o;
        }
        if (r + 8 < M) {
            float2 o;
            o.x = fmaxf(acc[t][2] + b0, 0.f);
            o.y = fmaxf(acc[t][3] + b1, 0.f);
            *(float2*)(out + (size_t)(r + 8) * CH + n) = o;
        }
    }
}

// ---------------- launch ----------------
extern "C" void kernel_launch(void* const* d_in, const int* in_sizes, int n_in,
                              void* d_out, int out_size)
{
    const float* x     = (const float*)d_in[0];
    const void*  eidx  = d_in[1];
    const float* eattr = (const float*)d_in[2];
    const float* W_enc = (const float*)d_in[3];
    const float* b_enc = (const float*)d_in[4];
    const float* We1   = (const float*)d_in[5];
    const float* be1   = (const float*)d_in[6];
    const float* W11   = (const float*)d_in[7];
    const float* b11   = (const float*)d_in[8];
    const float* W12   = (const float*)d_in[9];
    const float* b12   = (const float*)d_in[10];
    const float* eps1  = (const float*)d_in[11];
    const float* We2   = (const float*)d_in[12];
    const float* be2   = (const float*)d_in[13];
    const float* W21   = (const float*)d_in[14];
    const float* b21   = (const float*)d_in[15];
    const float* W22   = (const float*)d_in[16];
    const float* b22   = (const float*)d_in[17];
    const float* eps2  = (const float*)d_in[18];

    const int N = in_sizes[0] / CH;
    const int E = in_sizes[2] / 16;
    float* out = (float*)d_out;

    float *hP, *aggP, *zP;
    cudaGetSymbolAddress((void**)&hP, g_h);
    cudaGetSymbolAddress((void**)&aggP, g_agg);
    cudaGetSymbolAddress((void**)&zP, g_z);

    const int SMEM = 4 * 128 * LDP * 2 + 128 * 4;  // 139776 B
    cudaFuncSetAttribute((const void*)gemm_tc<false>,
                         cudaFuncAttributeMaxDynamicSharedMemorySize, SMEM);
    cudaFuncSetAttribute((const void*)gemm_tc<true>,
                         cudaFuncAttributeMaxDynamicSharedMemorySize, SMEM);

    detect_idx_kernel<<<1, 256>>>((const unsigned*)eidx, 2 * E);
    convert_idx_kernel<<<(E + 255) / 256, 256>>>(eidx, E);

    const int gb = (N + 127) / 128;

    // encoder
    gemm_tc<false><<<gb, 256, SMEM>>>(x, nullptr, nullptr, W_enc, b_enc, hP, N);

    // ---- conv1 ----
    zero_kernel<<<1184, 256>>>((float4*)aggP, N * CH / 4);
    msg_scatter<<<2368, 256>>>(hP, eattr, We1, be1, aggP, E);
    gemm_tc<true><<<gb, 256, SMEM>>>(hP, aggP, eps1, W11, b11, zP, N);
    gemm_tc<false><<<gb, 256, SMEM>>>(zP, nullptr, nullptr, W12, b12, hP, N);

    // ---- conv2 ----
    zero_kernel<<<1184, 256>>>((float4*)aggP, N * CH / 4);
    msg_scatter<<<2368, 256>>>(hP, eattr, We2, be2, aggP, E);
    gemm_tc<true><<<gb, 256, SMEM>>>(hP, aggP, eps2, W21, b21, zP, N);
    gemm_tc<false><<<gb, 256, SMEM>>>(zP, nullptr, nullptr, W22, b22, out, N);
}

// round 3
// speedup vs baseline: 1.3636x; 1.0229x over previous
#include <cuda_runtime.h>
#include <cuda_bf16.h>
#include <cstdint>
#include <cstddef>

#define NMAX 200000
#define EMAX 600000
#define CH 128
#define LDP 136  // padded row length in bf16 elems (conflict-free ldmatrix)

// ---------------- scratch (device globals; no allocation allowed) ----------------
__device__ float g_h[(size_t)NMAX * CH];
__device__ float g_agg[(size_t)NMAX * CH];
__device__ int   g_src[EMAX];
__device__ int   g_dst[EMAX];
__device__ int   g_idx64;

// ---------------- edge_index dtype sniffer ----------------
__global__ void detect_idx_kernel(const unsigned* __restrict__ p, int nwords)
{
    __shared__ unsigned s[32];
    unsigned v = 0;
    for (int i = threadIdx.x; i < 4096; i += blockDim.x) {
        int w = 2 * i + 1;
        if (w < nwords) v |= p[w];
    }
#pragma unroll
    for (int o = 16; o > 0; o >>= 1) v |= __shfl_xor_sync(0xffffffffu, v, o);
    int lane = threadIdx.x & 31, wid = threadIdx.x >> 5;
    if (lane == 0) s[wid] = v;
    __syncthreads();
    if (threadIdx.x == 0) {
        unsigned r = 0;
        int nw = (blockDim.x + 31) >> 5;
        for (int i = 0; i < nw; i++) r |= s[i];
        g_idx64 = (r == 0) ? 1 : 0;
    }
}

__global__ void convert_idx_kernel(const void* __restrict__ ei, int E)
{
    int i = blockIdx.x * blockDim.x + threadIdx.x;
    if (i >= E) return;
    if (g_idx64) {
        const long long* p = (const long long*)ei;
        g_src[i] = (int)p[i];
        g_dst[i] = (int)p[(size_t)E + i];
    } else {
        const int* p = (const int*)ei;
        g_src[i] = p[i];
        g_dst[i] = p[E + i];
    }
}

// ---------------- zero fill ----------------
__global__ void zero_kernel(float4* __restrict__ p, int n4)
{
    int i = blockIdx.x * blockDim.x + threadIdx.x;
    int stride = gridDim.x * blockDim.x;
    float4 z = make_float4(0.f, 0.f, 0.f, 0.f);
    for (; i < n4; i += stride) p[i] = z;
}

// ---------------- fused edge-GEMM + message + scatter-add ----------------
__global__ __launch_bounds__(256)
void msg_scatter(const float* __restrict__ h, const float* __restrict__ eattr,
                 const float* __restrict__ We, const float* __restrict__ be,
                 float* __restrict__ agg, int E)
{
    __shared__ float4 Wes[16][32];
    __shared__ float4 bes[32];
    int tid = threadIdx.x;
    for (int i = tid; i < 16 * 32; i += 256)
        ((float4*)Wes)[i] = ((const float4*)We)[i];
    if (tid < 32) bes[tid] = ((const float4*)be)[tid];
    __syncthreads();

    int lane = tid & 31;
    int gw = (blockIdx.x * 256 + tid) >> 5;
    int nw = (gridDim.x * 256) >> 5;

    for (int e = gw; e < E; e += nw) {
        int s = g_src[e];
        int d = g_dst[e];
        const float4* ea = ((const float4*)eattr) + (size_t)e * 4;
        float4 e0 = __ldg(ea + 0), e1 = __ldg(ea + 1);
        float4 e2 = __ldg(ea + 2), e3 = __ldg(ea + 3);
        float ev[16] = {e0.x, e0.y, e0.z, e0.w, e1.x, e1.y, e1.z, e1.w,
                        e2.x, e2.y, e2.z, e2.w, e3.x, e3.y, e3.z, e3.w};
        float4 acc = bes[lane];
#pragma unroll
        for (int k = 0; k < 16; k++) {
            float4 w = Wes[k][lane];
            acc.x += ev[k] * w.x;
            acc.y += ev[k] * w.y;
            acc.z += ev[k] * w.z;
            acc.w += ev[k] * w.w;
        }
        float4 hv = *(const float4*)(h + (size_t)s * CH + lane * 4);
        float mx = fmaxf(hv.x + acc.x, 0.f);
        float my = fmaxf(hv.y + acc.y, 0.f);
        float mz = fmaxf(hv.z + acc.z, 0.f);
        float mw = fmaxf(hv.w + acc.w, 0.f);
        size_t gaddr = __cvta_generic_to_global(agg + (size_t)d * CH + lane * 4);
        asm volatile("red.global.add.v4.f32 [%0], {%1,%2,%3,%4};"
                     :: "l"(gaddr), "f"(mx), "f"(my), "f"(mz), "f"(mw)
                     : "memory");
    }
}

// ---------------- tensor-core helpers (split-bf16, 3-term) ----------------
__device__ __forceinline__ void split_bf16(float v, __nv_bfloat16& h, __nv_bfloat16& l)
{
    h = __float2bfloat16(v);
    l = __float2bfloat16(v - __bfloat162float(h));
}

__device__ __forceinline__ uint32_t pack_split_hi(float a, float b)
{
    __nv_bfloat16 ha = __float2bfloat16(a), hb = __float2bfloat16(b);
    return ((uint32_t)__bfloat16_as_ushort(hb) << 16) | __bfloat16_as_ushort(ha);
}

__device__ __forceinline__ uint32_t pack_split_lo(float a, float b)
{
    __nv_bfloat16 ha = __float2bfloat16(a), hb = __float2bfloat16(b);
    __nv_bfloat16 la = __float2bfloat16(a - __bfloat162float(ha));
    __nv_bfloat16 lb = __float2bfloat16(b - __bfloat162float(hb));
    return ((uint32_t)__bfloat16_as_ushort(lb) << 16) | __bfloat16_as_ushort(la);
}

__device__ __forceinline__ void ldsm_x4(uint32_t& r0, uint32_t& r1, uint32_t& r2, uint32_t& r3,
                                        const void* p)
{
    uint32_t a = (uint32_t)__cvta_generic_to_shared(p);
    asm volatile("ldmatrix.sync.aligned.m8n8.x4.shared.b16 {%0,%1,%2,%3}, [%4];"
                 : "=r"(r0), "=r"(r1), "=r"(r2), "=r"(r3) : "r"(a));
}

__device__ __forceinline__ void ldsm_x4_t(uint32_t& r0, uint32_t& r1, uint32_t& r2, uint32_t& r3,
                                          const void* p)
{
    uint32_t a = (uint32_t)__cvta_generic_to_shared(p);
    asm volatile("ldmatrix.sync.aligned.m8n8.x4.trans.shared.b16 {%0,%1,%2,%3}, [%4];"
                 : "=r"(r0), "=r"(r1), "=r"(r2), "=r"(r3) : "r"(a));
}

__device__ __forceinline__ void mma_bf16(float* c, const uint32_t* a, uint32_t b0, uint32_t b1)
{
    asm volatile("mma.sync.aligned.m16n8k16.row.col.f32.bf16.bf16.f32 "
                 "{%0,%1,%2,%3}, {%4,%5,%6,%7}, {%8,%9}, {%0,%1,%2,%3};"
                 : "+f"(c[0]), "+f"(c[1]), "+f"(c[2]), "+f"(c[3])
                 : "r"(a[0]), "r"(a[1]), "r"(a[2]), "r"(a[3]), "r"(b0), "r"(b1));
}

// stage a 128x128 fp32 matrix into hi/lo bf16 smem planes (padded LDP)
__device__ __forceinline__ void stage_w(const float* __restrict__ W,
                                        __nv_bfloat16* Wh, __nv_bfloat16* Wl, int tid)
{
#pragma unroll
    for (int i = 0; i < 16; i++) {
        int idx = tid + i * 256;  // float4 idx 0..4095
        int k = idx >> 5, c4 = idx & 31;
        float4 v = ((const float4*)W)[idx];
        __nv_bfloat16 h0, l0;
        split_bf16(v.x, h0, l0); Wh[k * LDP + c4 * 4 + 0] = h0; Wl[k * LDP + c4 * 4 + 0] = l0;
        split_bf16(v.y, h0, l0); Wh[k * LDP + c4 * 4 + 1] = h0; Wl[k * LDP + c4 * 4 + 1] = l0;
        split_bf16(v.z, h0, l0); Wh[k * LDP + c4 * 4 + 2] = h0; Wl[k * LDP + c4 * 4 + 2] = l0;
        split_bf16(v.w, h0, l0); Wh[k * LDP + c4 * 4 + 3] = h0; Wl[k * LDP + c4 * 4 + 3] = l0;
    }
}

// one 3-term split-bf16 GEMM pass over smem operands; acc[16][4] for warp's 16 rows x 128 cols
__device__ __forceinline__ void mma_pass(const __nv_bfloat16* Ah, const __nv_bfloat16* Al,
                                         const __nv_bfloat16* Bh, const __nv_bfloat16* Bl,
                                         int lane, int m0, float acc[16][4])
{
#pragma unroll
    for (int t = 0; t < 16; t++)
#pragma unroll
        for (int j = 0; j < 4; j++) acc[t][j] = 0.f;

    const int arow = m0 + (lane & 15);
    const int aoff = ((lane >> 4) << 3);

#pragma unroll
    for (int kc = 0; kc < 8; kc++) {
        const int kb = kc * 16;
        uint32_t ah[4], al[4];
        ldsm_x4(ah[0], ah[1], ah[2], ah[3], Ah + arow * LDP + kb + aoff);
        ldsm_x4(al[0], al[1], al[2], al[3], Al + arow * LDP + kb + aoff);
        const int brow = kb + (lane & 15);
#pragma unroll
        for (int ng = 0; ng < 8; ng++) {
            const int n0 = ng * 16;
            uint32_t bh[4], bl[4];
            ldsm_x4_t(bh[0], bh[1], bh[2], bh[3], Bh + brow * LDP + n0 + aoff);
            ldsm_x4_t(bl[0], bl[1], bl[2], bl[3], Bl + brow * LDP + n0 + aoff);
            float* c0 = acc[ng * 2];
            float* c1 = acc[ng * 2 + 1];
            mma_bf16(c0, ah, bh[0], bh[1]);
            mma_bf16(c0, al, bh[0], bh[1]);
            mma_bf16(c0, ah, bl[0], bl[1]);
            mma_bf16(c1, ah, bh[2], bh[3]);
            mma_bf16(c1, al, bh[2], bh[3]);
            mma_bf16(c1, ah, bl[2], bl[3]);
        }
    }
}

// ---------------- single GEMM + bias + ReLU (encoder) ----------------
__global__ __launch_bounds__(256)
void gemm_tc(const float* __restrict__ A,
             const float* __restrict__ W, const float* __restrict__ bias,
             float* __restrict__ out, int M)
{
    extern __shared__ char smraw[];
    __nv_bfloat16* Ah = (__nv_bfloat16*)smraw;
    __nv_bfloat16* Al = Ah + 128 * LDP;
    __nv_bfloat16* Bh = Al + 128 * LDP;
    __nv_bfloat16* Bl = Bh + 128 * LDP;
    float* sbias = (float*)(Bl + 128 * LDP);

    const int tid = threadIdx.x;
    const int row0 = blockIdx.x * 128;

    if (tid < 128) sbias[tid] = __ldg(bias + tid);
    stage_w(W, Bh, Bl, tid);

#pragma unroll
    for (int i = 0; i < 16; i++) {
        int idx = tid + i * 256;
        int r = idx >> 5, c4 = idx & 31;
        int g = row0 + r;
        float4 v = make_float4(0.f, 0.f, 0.f, 0.f);
        if (g < M) v = ((const float4*)(A + (size_t)g * CH))[c4];
        __nv_bfloat16 h0, l0;
        split_bf16(v.x, h0, l0); Ah[r * LDP + c4 * 4 + 0] = h0; Al[r * LDP + c4 * 4 + 0] = l0;
        split_bf16(v.y, h0, l0); Ah[r * LDP + c4 * 4 + 1] = h0; Al[r * LDP + c4 * 4 + 1] = l0;
        split_bf16(v.z, h0, l0); Ah[r * LDP + c4 * 4 + 2] = h0; Al[r * LDP + c4 * 4 + 2] = l0;
        split_bf16(v.w, h0, l0); Ah[r * LDP + c4 * 4 + 3] = h0; Al[r * LDP + c4 * 4 + 3] = l0;
    }
    __syncthreads();

    const int warp = tid >> 5;
    const int lane = tid & 31;
    const int m0 = warp * 16;

    float acc[16][4];
    mma_pass(Ah, Al, Bh, Bl, lane, m0, acc);

    const int r = row0 + m0 + (lane >> 2);
    const int cb = (lane & 3) * 2;
#pragma unroll
    for (int t = 0; t < 16; t++) {
        const int n = t * 8 + cb;
        const float b0 = sbias[n], b1 = sbias[n + 1];
        if (r < M) {
            float2 o;
            o.x = fmaxf(acc[t][0] + b0, 0.f);
            o.y = fmaxf(acc[t][1] + b1, 0.f);
            *(float2*)(out + (size_t)r * CH + n) = o;
        }
        if (r + 8 < M) {
            float2 o;
            o.x = fmaxf(acc[t][2] + b0, 0.f);
            o.y = fmaxf(acc[t][3] + b1, 0.f);
            *(float2*)(out + (size_t)(r + 8) * CH + n) = o;
        }
    }
}

// ---------------- fused 2-layer MLP (one GINE conv update) ----------------
// out = relu( relu( ((1+eps)*A + AGG) @ W1 + b1 ) @ W2 + b2 )
// z tile never leaves the CTA: written to smem as split-bf16 (precision-identical
// to what the consumer GEMM splits to anyway), second GEMM runs from smem.
__global__ __launch_bounds__(256)
void gemm2_tc(const float* __restrict__ A, const float* __restrict__ AGG,
              const float* __restrict__ epsp,
              const float* __restrict__ W1, const float* __restrict__ b1,
              const float* __restrict__ W2, const float* __restrict__ b2,
              float* __restrict__ out, int M)
{
    extern __shared__ char smraw[];
    __nv_bfloat16* Ah  = (__nv_bfloat16*)smraw;    // A tile, reused as Z tile
    __nv_bfloat16* Al  = Ah  + 128 * LDP;
    __nv_bfloat16* B1h = Al  + 128 * LDP;
    __nv_bfloat16* B1l = B1h + 128 * LDP;
    __nv_bfloat16* B2h = B1l + 128 * LDP;
    __nv_bfloat16* B2l = B2h + 128 * LDP;
    float* sb1 = (float*)(B2l + 128 * LDP);
    float* sb2 = sb1 + 128;

    const int tid = threadIdx.x;
    const int row0 = blockIdx.x * 128;

    if (tid < 128) sb1[tid] = __ldg(b1 + tid);
    else if (tid < 256) sb2[tid - 128] = __ldg(b2 + tid - 128);

    stage_w(W1, B1h, B1l, tid);
    stage_w(W2, B2h, B2l, tid);

    const float epc = 1.0f + __ldg(epsp);

    // stage A tile with fused (1+eps)*h + agg transform
#pragma unroll
    for (int i = 0; i < 16; i++) {
        int idx = tid + i * 256;
        int r = idx >> 5, c4 = idx & 31;
        int g = row0 + r;
        float4 v = make_float4(0.f, 0.f, 0.f, 0.f);
        if (g < M) {
            v = ((const float4*)(A + (size_t)g * CH))[c4];
            float4 b = ((const float4*)(AGG + (size_t)g * CH))[c4];
            v.x = epc * v.x + b.x;
            v.y = epc * v.y + b.y;
            v.z = epc * v.z + b.z;
            v.w = epc * v.w + b.w;
        }
        __nv_bfloat16 h0, l0;
        split_bf16(v.x, h0, l0); Ah[r * LDP + c4 * 4 + 0] = h0; Al[r * LDP + c4 * 4 + 0] = l0;
        split_bf16(v.y, h0, l0); Ah[r * LDP + c4 * 4 + 1] = h0; Al[r * LDP + c4 * 4 + 1] = l0;
        split_bf16(v.z, h0, l0); Ah[r * LDP + c4 * 4 + 2] = h0; Al[r * LDP + c4 * 4 + 2] = l0;
        split_bf16(v.w, h0, l0); Ah[r * LDP + c4 * 4 + 3] = h0; Al[r * LDP + c4 * 4 + 3] = l0;
    }
    __syncthreads();

    const int warp = tid >> 5;
    const int lane = tid & 31;
    const int m0 = warp * 16;

    // ---- layer 1 ----
    float acc[16][4];
    mma_pass(Ah, Al, B1h, B1l, lane, m0, acc);

    __syncthreads();  // all warps done reading A tile before overwrite with Z

    // z = relu(acc + b1), split into hi/lo, store into Ah/Al (as Z planes)
    {
        const int rl0 = m0 + (lane >> 2);       // local row
        const int cb = (lane & 3) * 2;
#pragma unroll
        for (int t = 0; t < 16; t++) {
            const int n = t * 8 + cb;
            const float b0 = sb1[n], b1v = sb1[n + 1];
            float z0 = fmaxf(acc[t][0] + b0, 0.f);
            float z1 = fmaxf(acc[t][1] + b1v, 0.f);
            float z2 = fmaxf(acc[t][2] + b0, 0.f);
            float z3 = fmaxf(acc[t][3] + b1v, 0.f);
            *(uint32_t*)(Ah + rl0 * LDP + n)       = pack_split_hi(z0, z1);
            *(uint32_t*)(Al + rl0 * LDP + n)       = pack_split_lo(z0, z1);
            *(uint32_t*)(Ah + (rl0 + 8) * LDP + n) = pack_split_hi(z2, z3);
            *(uint32_t*)(Al + (rl0 + 8) * LDP + n) = pack_split_lo(z2, z3);
        }
    }
    __syncthreads();

    // ---- layer 2 ----
    mma_pass(Ah, Al, B2h, B2l, lane, m0, acc);

    const int r = row0 + m0 + (lane >> 2);
    const int cb = (lane & 3) * 2;
#pragma unroll
    for (int t = 0; t < 16; t++) {
        const int n = t * 8 + cb;
        const float b0 = sb2[n], b1v = sb2[n + 1];
        if (r < M) {
            float2 o;
            o.x = fmaxf(acc[t][0] + b0, 0.f);
            o.y = fmaxf(acc[t][1] + b1v, 0.f);
            *(float2*)(out + (size_t)r * CH + n) = o;
        }
        if (r + 8 < M) {
            float2 o;
            o.x = fmaxf(acc[t][2] + b0, 0.f);
            o.y = fmaxf(acc[t][3] + b1v, 0.f);
            *(float2*)(out + (size_t)(r + 8) * CH + n) = o;
        }
    }
}

// ---------------- launch ----------------
extern "C" void kernel_launch(void* const* d_in, const int* in_sizes, int n_in,
                              void* d_out, int out_size)
{
    const float* x     = (const float*)d_in[0];
    const void*  eidx  = d_in[1];
    const float* eattr = (const float*)d_in[2];
    const float* W_enc = (const float*)d_in[3];
    const float* b_enc = (const float*)d_in[4];
    const float* We1   = (const float*)d_in[5];
    const float* be1   = (const float*)d_in[6];
    const float* W11   = (const float*)d_in[7];
    const float* b11   = (const float*)d_in[8];
    const float* W12   = (const float*)d_in[9];
    const float* b12   = (const float*)d_in[10];
    const float* eps1  = (const float*)d_in[11];
    const float* We2   = (const float*)d_in[12];
    const float* be2   = (const float*)d_in[13];
    const float* W21   = (const float*)d_in[14];
    const float* b21   = (const float*)d_in[15];
    const float* W22   = (const float*)d_in[16];
    const float* b22   = (const float*)d_in[17];
    const float* eps2  = (const float*)d_in[18];

    const int N = in_sizes[0] / CH;
    const int E = in_sizes[2] / 16;
    float* out = (float*)d_out;

    float *hP, *aggP;
    cudaGetSymbolAddress((void**)&hP, g_h);
    cudaGetSymbolAddress((void**)&aggP, g_agg);

    const int SMEM1 = 4 * 128 * LDP * 2 + 128 * 4;            // 139,776 B
    const int SMEM2 = 6 * 128 * LDP * 2 + 2 * 128 * 4;        // 209,920 B
    cudaFuncSetAttribute((const void*)gemm_tc,
                         cudaFuncAttributeMaxDynamicSharedMemorySize, SMEM1);
    cudaFuncSetAttribute((const void*)gemm2_tc,
                         cudaFuncAttributeMaxDynamicSharedMemorySize, SMEM2);

    detect_idx_kernel<<<1, 256>>>((const unsigned*)eidx, 2 * E);
    convert_idx_kernel<<<(E + 255) / 256, 256>>>(eidx, E);

    const int gb = (N + 127) / 128;

    // encoder
    gemm_tc<<<gb, 256, SMEM1>>>(x, W_enc, b_enc, hP, N);

    // ---- conv1 ----
    zero_kernel<<<1184, 256>>>((float4*)aggP, N * CH / 4);
    msg_scatter<<<2368, 256>>>(hP, eattr, We1, be1, aggP, E);
    gemm2_tc<<<gb, 256, SMEM2>>>(hP, aggP, eps1, W11, b11, W12, b12, hP, N);  // in-place

    // ---- conv2 ----
    zero_kernel<<<1184, 256>>>((float4*)aggP, N * CH / 4);
    msg_scatter<<<2368, 256>>>(hP, eattr, We2, be2, aggP, E);
    gemm2_tc<<<gb, 256, SMEM2>>>(hP, aggP, eps2, W21, b21, W22, b22, out, N);
}

// round 4
// speedup vs baseline: 1.4181x; 1.0399x over previous
#include <cuda_runtime.h>
#include <cuda_bf16.h>
#include <cstdint>
#include <cstddef>

#define NMAX 200000
#define EMAX 600000
#define CH 128
#define LDP 136  // padded row length in bf16 elems (conflict-free ldmatrix)

// ---------------- scratch (device globals; no allocation allowed) ----------------
__device__ float g_h[(size_t)NMAX * CH];
__device__ float g_agg[(size_t)NMAX * CH];
__device__ int   g_src[EMAX];
__device__ int   g_dst[EMAX];
__device__ int   g_cnt[NMAX];
__device__ int   g_off[NMAX + 1];
__device__ int   g_cur[NMAX];
__device__ int   g_esrc[EMAX];
__device__ int   g_eeid[EMAX];
__device__ int   g_bsum[256];
__device__ int   g_bbase[256];
__device__ int   g_idx64;

// ---------------- edge_index dtype sniffer ----------------
__global__ void detect_idx_kernel(const unsigned* __restrict__ p, int nwords)
{
    __shared__ unsigned s[32];
    unsigned v = 0;
    for (int i = threadIdx.x; i < 4096; i += blockDim.x) {
        int w = 2 * i + 1;
        if (w < nwords) v |= p[w];
    }
#pragma unroll
    for (int o = 16; o > 0; o >>= 1) v |= __shfl_xor_sync(0xffffffffu, v, o);
    int lane = threadIdx.x & 31, wid = threadIdx.x >> 5;
    if (lane == 0) s[wid] = v;
    __syncthreads();
    if (threadIdx.x == 0) {
        unsigned r = 0;
        int nw = (blockDim.x + 31) >> 5;
        for (int i = 0; i < nw; i++) r |= s[i];
        g_idx64 = (r == 0) ? 1 : 0;
    }
}

// ---------------- CSR build ----------------
__global__ void zero_counts_kernel(int N)
{
    int i = blockIdx.x * blockDim.x + threadIdx.x;
    if (i < N) g_cnt[i] = 0;
}

// convert edge_index to int32 src/dst and histogram dst
__global__ void convert_hist_kernel(const void* __restrict__ ei, int E)
{
    int i = blockIdx.x * blockDim.x + threadIdx.x;
    if (i >= E) return;
    int s, d;
    if (g_idx64) {
        const long long* p = (const long long*)ei;
        s = (int)p[i];
        d = (int)p[(size_t)E + i];
    } else {
        const int* p = (const int*)ei;
        s = p[i];
        d = p[E + i];
    }
    g_src[i] = s;
    g_dst[i] = d;
    atomicAdd(&g_cnt[d], 1);
}

// per-block partial sums of g_cnt
__global__ void scan1_kernel(int N)
{
    __shared__ int s[32];
    int idx = blockIdx.x * 1024 + threadIdx.x;
    int v = (idx < N) ? g_cnt[idx] : 0;
    int t = v;
#pragma unroll
    for (int o = 16; o > 0; o >>= 1) t += __shfl_xor_sync(0xffffffffu, t, o);
    if ((threadIdx.x & 31) == 0) s[threadIdx.x >> 5] = t;
    __syncthreads();
    if (threadIdx.x == 0) {
        int r = 0;
        for (int i = 0; i < 32; i++) r += s[i];
        g_bsum[blockIdx.x] = r;
    }
}

// exclusive scan of block sums (nb <= 256), also write offsets[N] = E
__global__ void scan2_kernel(int nb, int N, int E)
{
    __shared__ int s[256];
    int t = threadIdx.x;
    int v = (t < nb) ? g_bsum[t] : 0;
    s[t] = v;
    __syncthreads();
#pragma unroll
    for (int o = 1; o < 256; o <<= 1) {
        int nv = s[t];
        if (t >= o) nv += s[t - o];
        __syncthreads();
        s[t] = nv;
        __syncthreads();
    }
    if (t < nb) g_bbase[t] = s[t] - v;  // exclusive
    if (t == 0) g_off[N] = E;
}

// per-block exclusive scan + base -> offsets, cursor
__global__ void scan3_kernel(int N)
{
    __shared__ int s[1024];
    int idx = blockIdx.x * 1024 + threadIdx.x;
    int t = threadIdx.x;
    int v = (idx < N) ? g_cnt[idx] : 0;
    s[t] = v;
    __syncthreads();
#pragma unroll
    for (int o = 1; o < 1024; o <<= 1) {
        int nv = s[t];
        if (t >= o) nv += s[t - o];
        __syncthreads();
        s[t] = nv;
        __syncthreads();
    }
    if (idx < N) {
        int excl = g_bbase[blockIdx.x] + s[t] - v;
        g_off[idx] = excl;
        g_cur[idx] = excl;
    }
}

// place edges into dst-sorted order
__global__ void place_kernel(int E)
{
    int i = blockIdx.x * blockDim.x + threadIdx.x;
    if (i >= E) return;
    int d = g_dst[i];
    int p = atomicAdd(&g_cur[d], 1);
    g_esrc[p] = g_src[i];
    g_eeid[p] = i;
}

// ---------------- CSR aggregation: z[n] = (1+eps)*h[n] + sum relu(h[src]+ef) ----------------
// one warp per node; lane owns channels [4l,4l+4)
__global__ __launch_bounds__(256)
void aggregate_kernel(const float* __restrict__ h, const float* __restrict__ eattr,
                      const float* __restrict__ We, const float* __restrict__ be,
                      const float* __restrict__ epsp,
                      float* __restrict__ z, int N)
{
    __shared__ float4 Wes[16][32];
    __shared__ float4 bes[32];
    int tid = threadIdx.x;
    for (int i = tid; i < 16 * 32; i += 256)
        ((float4*)Wes)[i] = ((const float4*)We)[i];
    if (tid < 32) bes[tid] = ((const float4*)be)[tid];
    __syncthreads();

    const float epc = 1.0f + __ldg(epsp);
    const int lane = tid & 31;
    int gw = (blockIdx.x * 256 + tid) >> 5;
    int nw = (gridDim.x * 256) >> 5;

    for (int n = gw; n < N; n += nw) {
        float4 hv = *(const float4*)(h + (size_t)n * CH + lane * 4);
        float4 acc;
        acc.x = epc * hv.x;
        acc.y = epc * hv.y;
        acc.z = epc * hv.z;
        acc.w = epc * hv.w;

        const int p0 = __ldg(&g_off[n]);
        const int p1 = __ldg(&g_off[n + 1]);
        for (int p = p0; p < p1; ++p) {
            int s = __ldg(&g_esrc[p]);
            int eid = __ldg(&g_eeid[p]);
            const float4* ea = ((const float4*)eattr) + (size_t)eid * 4;
            float4 e0 = __ldg(ea + 0), e1 = __ldg(ea + 1);
            float4 e2 = __ldg(ea + 2), e3 = __ldg(ea + 3);
            float ev[16] = {e0.x, e0.y, e0.z, e0.w, e1.x, e1.y, e1.z, e1.w,
                            e2.x, e2.y, e2.z, e2.w, e3.x, e3.y, e3.z, e3.w};
            float4 m = bes[lane];
#pragma unroll
            for (int k = 0; k < 16; k++) {
                float4 w = Wes[k][lane];
                m.x += ev[k] * w.x;
                m.y += ev[k] * w.y;
                m.z += ev[k] * w.z;
                m.w += ev[k] * w.w;
            }
            float4 sv = *(const float4*)(h + (size_t)s * CH + lane * 4);
            acc.x += fmaxf(sv.x + m.x, 0.f);
            acc.y += fmaxf(sv.y + m.y, 0.f);
            acc.z += fmaxf(sv.z + m.z, 0.f);
            acc.w += fmaxf(sv.w + m.w, 0.f);
        }
        *(float4*)(z + (size_t)n * CH + lane * 4) = acc;
    }
}

// ---------------- tensor-core helpers (split-bf16, 3-term) ----------------
__device__ __forceinline__ void split_bf16(float v, __nv_bfloat16& h, __nv_bfloat16& l)
{
    h = __float2bfloat16(v);
    l = __float2bfloat16(v - __bfloat162float(h));
}

__device__ __forceinline__ uint32_t pack_split_hi(float a, float b)
{
    __nv_bfloat16 ha = __float2bfloat16(a), hb = __float2bfloat16(b);
    return ((uint32_t)__bfloat16_as_ushort(hb) << 16) | __bfloat16_as_ushort(ha);
}

__device__ __forceinline__ uint32_t pack_split_lo(float a, float b)
{
    __nv_bfloat16 ha = __float2bfloat16(a), hb = __float2bfloat16(b);
    __nv_bfloat16 la = __float2bfloat16(a - __bfloat162float(ha));
    __nv_bfloat16 lb = __float2bfloat16(b - __bfloat162float(hb));
    return ((uint32_t)__bfloat16_as_ushort(lb) << 16) | __bfloat16_as_ushort(la);
}

__device__ __forceinline__ void ldsm_x4(uint32_t& r0, uint32_t& r1, uint32_t& r2, uint32_t& r3,
                                        const void* p)
{
    uint32_t a = (uint32_t)__cvta_generic_to_shared(p);
    asm volatile("ldmatrix.sync.aligned.m8n8.x4.shared.b16 {%0,%1,%2,%3}, [%4];"
                 : "=r"(r0), "=r"(r1), "=r"(r2), "=r"(r3) : "r"(a));
}

__device__ __forceinline__ void ldsm_x4_t(uint32_t& r0, uint32_t& r1, uint32_t& r2, uint32_t& r3,
                                          const void* p)
{
    uint32_t a = (uint32_t)__cvta_generic_to_shared(p);
    asm volatile("ldmatrix.sync.aligned.m8n8.x4.trans.shared.b16 {%0,%1,%2,%3}, [%4];"
                 : "=r"(r0), "=r"(r1), "=r"(r2), "=r"(r3) : "r"(a));
}

__device__ __forceinline__ void mma_bf16(float* c, const uint32_t* a, uint32_t b0, uint32_t b1)
{
    asm volatile("mma.sync.aligned.m16n8k16.row.col.f32.bf16.bf16.f32 "
                 "{%0,%1,%2,%3}, {%4,%5,%6,%7}, {%8,%9}, {%0,%1,%2,%3};"
                 : "+f"(c[0]), "+f"(c[1]), "+f"(c[2]), "+f"(c[3])
                 : "r"(a[0]), "r"(a[1]), "r"(a[2]), "r"(a[3]), "r"(b0), "r"(b1));
}

__device__ __forceinline__ void stage_w(const float* __restrict__ W,
                                        __nv_bfloat16* Wh, __nv_bfloat16* Wl, int tid)
{
#pragma unroll
    for (int i = 0; i < 16; i++) {
        int idx = tid + i * 256;
        int k = idx >> 5, c4 = idx & 31;
        float4 v = ((const float4*)W)[idx];
        __nv_bfloat16 h0, l0;
        split_bf16(v.x, h0, l0); Wh[k * LDP + c4 * 4 + 0] = h0; Wl[k * LDP + c4 * 4 + 0] = l0;
        split_bf16(v.y, h0, l0); Wh[k * LDP + c4 * 4 + 1] = h0; Wl[k * LDP + c4 * 4 + 1] = l0;
        split_bf16(v.z, h0, l0); Wh[k * LDP + c4 * 4 + 2] = h0; Wl[k * LDP + c4 * 4 + 2] = l0;
        split_bf16(v.w, h0, l0); Wh[k * LDP + c4 * 4 + 3] = h0; Wl[k * LDP + c4 * 4 + 3] = l0;
    }
}

__device__ __forceinline__ void stage_a(const float* __restrict__ A,
                                        __nv_bfloat16* Ah, __nv_bfloat16* Al,
                                        int tid, int row0, int M)
{
#pragma unroll
    for (int i = 0; i < 16; i++) {
        int idx = tid + i * 256;
        int r = idx >> 5, c4 = idx & 31;
        int g = row0 + r;
        float4 v = make_float4(0.f, 0.f, 0.f, 0.f);
        if (g < M) v = ((const float4*)(A + (size_t)g * CH))[c4];
        __nv_bfloat16 h0, l0;
        split_bf16(v.x, h0, l0); Ah[r * LDP + c4 * 4 + 0] = h0; Al[r * LDP + c4 * 4 + 0] = l0;
        split_bf16(v.y, h0, l0); Ah[r * LDP + c4 * 4 + 1] = h0; Al[r * LDP + c4 * 4 + 1] = l0;
        split_bf16(v.z, h0, l0); Ah[r * LDP + c4 * 4 + 2] = h0; Al[r * LDP + c4 * 4 + 2] = l0;
        split_bf16(v.w, h0, l0); Ah[r * LDP + c4 * 4 + 3] = h0; Al[r * LDP + c4 * 4 + 3] = l0;
    }
}

__device__ __forceinline__ void mma_pass(const __nv_bfloat16* Ah, const __nv_bfloat16* Al,
                                         const __nv_bfloat16* Bh, const __nv_bfloat16* Bl,
                                         int lane, int m0, float acc[16][4])
{
#pragma unroll
    for (int t = 0; t < 16; t++)
#pragma unroll
        for (int j = 0; j < 4; j++) acc[t][j] = 0.f;

    const int arow = m0 + (lane & 15);
    const int aoff = ((lane >> 4) << 3);

#pragma unroll
    for (int kc = 0; kc < 8; kc++) {
        const int kb = kc * 16;
        uint32_t ah[4], al[4];
        ldsm_x4(ah[0], ah[1], ah[2], ah[3], Ah + arow * LDP + kb + aoff);
        ldsm_x4(al[0], al[1], al[2], al[3], Al + arow * LDP + kb + aoff);
        const int brow = kb + (lane & 15);
#pragma unroll
        for (int ng = 0; ng < 8; ng++) {
            const int n0 = ng * 16;
            uint32_t bh[4], bl[4];
            ldsm_x4_t(bh[0], bh[1], bh[2], bh[3], Bh + brow * LDP + n0 + aoff);
            ldsm_x4_t(bl[0], bl[1], bl[2], bl[3], Bl + brow * LDP + n0 + aoff);
            float* c0 = acc[ng * 2];
            float* c1 = acc[ng * 2 + 1];
            mma_bf16(c0, ah, bh[0], bh[1]);
            mma_bf16(c0, al, bh[0], bh[1]);
            mma_bf16(c0, ah, bl[0], bl[1]);
            mma_bf16(c1, ah, bh[2], bh[3]);
            mma_bf16(c1, al, bh[2], bh[3]);
            mma_bf16(c1, ah, bl[2], bl[3]);
        }
    }
}

// ---------------- single GEMM + bias + ReLU (encoder) ----------------
__global__ __launch_bounds__(256)
void gemm_tc(const float* __restrict__ A,
             const float* __restrict__ W, const float* __restrict__ bias,
             float* __restrict__ out, int M)
{
    extern __shared__ char smraw[];
    __nv_bfloat16* Ah = (__nv_bfloat16*)smraw;
    __nv_bfloat16* Al = Ah + 128 * LDP;
    __nv_bfloat16* Bh = Al + 128 * LDP;
    __nv_bfloat16* Bl = Bh + 128 * LDP;
    float* sbias = (float*)(Bl + 128 * LDP);

    const int tid = threadIdx.x;
    const int row0 = blockIdx.x * 128;

    if (tid < 128) sbias[tid] = __ldg(bias + tid);
    stage_w(W, Bh, Bl, tid);
    stage_a(A, Ah, Al, tid, row0, M);
    __syncthreads();

    const int warp = tid >> 5;
    const int lane = tid & 31;
    const int m0 = warp * 16;

    float acc[16][4];
    mma_pass(Ah, Al, Bh, Bl, lane, m0, acc);

    const int r = row0 + m0 + (lane >> 2);
    const int cb = (lane & 3) * 2;
#pragma unroll
    for (int t = 0; t < 16; t++) {
        const int n = t * 8 + cb;
        const float b0 = sbias[n], b1 = sbias[n + 1];
        if (r < M) {
            float2 o;
            o.x = fmaxf(acc[t][0] + b0, 0.f);
            o.y = fmaxf(acc[t][1] + b1, 0.f);
            *(float2*)(out + (size_t)r * CH + n) = o;
        }
        if (r + 8 < M) {
            float2 o;
            o.x = fmaxf(acc[t][2] + b0, 0.f);
            o.y = fmaxf(acc[t][3] + b1, 0.f);
            *(float2*)(out + (size_t)(r + 8) * CH + n) = o;
        }
    }
}

// ---------------- fused 2-layer MLP: out = relu(relu(A@W1+b1)@W2+b2) ----------------
__global__ __launch_bounds__(256)
void gemm2_tc(const float* __restrict__ A,
              const float* __restrict__ W1, const float* __restrict__ b1,
              const float* __restrict__ W2, const float* __restrict__ b2,
              float* __restrict__ out, int M)
{
    extern __shared__ char smraw[];
    __nv_bfloat16* Ah  = (__nv_bfloat16*)smraw;    // A tile, reused as Z tile
    __nv_bfloat16* Al  = Ah  + 128 * LDP;
    __nv_bfloat16* B1h = Al  + 128 * LDP;
    __nv_bfloat16* B1l = B1h + 128 * LDP;
    __nv_bfloat16* B2h = B1l + 128 * LDP;
    __nv_bfloat16* B2l = B2h + 128 * LDP;
    float* sb1 = (float*)(B2l + 128 * LDP);
    float* sb2 = sb1 + 128;

    const int tid = threadIdx.x;
    const int row0 = blockIdx.x * 128;

    if (tid < 128) sb1[tid] = __ldg(b1 + tid);
    else if (tid < 256) sb2[tid - 128] = __ldg(b2 + tid - 128);

    stage_w(W1, B1h, B1l, tid);
    stage_w(W2, B2h, B2l, tid);
    stage_a(A, Ah, Al, tid, row0, M);
    __syncthreads();

    const int warp = tid >> 5;
    const int lane = tid & 31;
    const int m0 = warp * 16;

    float acc[16][4];
    mma_pass(Ah, Al, B1h, B1l, lane, m0, acc);

    __syncthreads();

    {
        const int rl0 = m0 + (lane >> 2);
        const int cb = (lane & 3) * 2;
#pragma unroll
        for (int t = 0; t < 16; t++) {
            const int n = t * 8 + cb;
            const float b0 = sb1[n], b1v = sb1[n + 1];
            float z0 = fmaxf(acc[t][0] + b0, 0.f);
            float z1 = fmaxf(acc[t][1] + b1v, 0.f);
            float z2 = fmaxf(acc[t][2] + b0, 0.f);
            float z3 = fmaxf(acc[t][3] + b1v, 0.f);
            *(uint32_t*)(Ah + rl0 * LDP + n)       = pack_split_hi(z0, z1);
            *(uint32_t*)(Al + rl0 * LDP + n)       = pack_split_lo(z0, z1);
            *(uint32_t*)(Ah + (rl0 + 8) * LDP + n) = pack_split_hi(z2, z3);
            *(uint32_t*)(Al + (rl0 + 8) * LDP + n) = pack_split_lo(z2, z3);
        }
    }
    __syncthreads();

    mma_pass(Ah, Al, B2h, B2l, lane, m0, acc);

    const int r = row0 + m0 + (lane >> 2);
    const int cb = (lane & 3) * 2;
#pragma unroll
    for (int t = 0; t < 16; t++) {
        const int n = t * 8 + cb;
        const float b0 = sb2[n], b1v = sb2[n + 1];
        if (r < M) {
            float2 o;
            o.x = fmaxf(acc[t][0] + b0, 0.f);
            o.y = fmaxf(acc[t][1] + b1v, 0.f);
            *(float2*)(out + (size_t)r * CH + n) = o;
        }
        if (r + 8 < M) {
            float2 o;
            o.x = fmaxf(acc[t][2] + b0, 0.f);
            o.y = fmaxf(acc[t][3] + b1v, 0.f);
            *(float2*)(out + (size_t)(r + 8) * CH + n) = o;
        }
    }
}

// ---------------- launch ----------------
extern "C" void kernel_launch(void* const* d_in, const int* in_sizes, int n_in,
                              void* d_out, int out_size)
{
    const float* x     = (const float*)d_in[0];
    const void*  eidx  = d_in[1];
    const float* eattr = (const float*)d_in[2];
    const float* W_enc = (const float*)d_in[3];
    const float* b_enc = (const float*)d_in[4];
    const float* We1   = (const float*)d_in[5];
    const float* be1   = (const float*)d_in[6];
    const float* W11   = (const float*)d_in[7];
    const float* b11   = (const float*)d_in[8];
    const float* W12   = (const float*)d_in[9];
    const float* b12   = (const float*)d_in[10];
    const float* eps1  = (const float*)d_in[11];
    const float* We2   = (const float*)d_in[12];
    const float* be2   = (const float*)d_in[13];
    const float* W21   = (const float*)d_in[14];
    const float* b21   = (const float*)d_in[15];
    const float* W22   = (const float*)d_in[16];
    const float* b22   = (const float*)d_in[17];
    const float* eps2  = (const float*)d_in[18];

    const int N = in_sizes[0] / CH;
    const int E = in_sizes[2] / 16;
    float* out = (float*)d_out;

    float *hP, *aggP;
    cudaGetSymbolAddress((void**)&hP, g_h);
    cudaGetSymbolAddress((void**)&aggP, g_agg);

    const int SMEM1 = 4 * 128 * LDP * 2 + 128 * 4;      // 139,776 B
    const int SMEM2 = 6 * 128 * LDP * 2 + 2 * 128 * 4;  // 209,920 B
    cudaFuncSetAttribute((const void*)gemm_tc,
                         cudaFuncAttributeMaxDynamicSharedMemorySize, SMEM1);
    cudaFuncSetAttribute((const void*)gemm2_tc,
                         cudaFuncAttributeMaxDynamicSharedMemorySize, SMEM2);

    const int nb = (N + 1023) / 1024;

    // ---- CSR build (shared by both convs) ----
    detect_idx_kernel<<<1, 256>>>((const unsigned*)eidx, 2 * E);
    zero_counts_kernel<<<nb, 1024>>>(N);
    convert_hist_kernel<<<(E + 255) / 256, 256>>>(eidx, E);
    scan1_kernel<<<nb, 1024>>>(N);
    scan2_kernel<<<1, 256>>>(nb, N, E);
    scan3_kernel<<<nb, 1024>>>(N);
    place_kernel<<<(E + 255) / 256, 256>>>(E);

    const int gb = (N + 127) / 128;

    // encoder
    gemm_tc<<<gb, 256, SMEM1>>>(x, W_enc, b_enc, hP, N);

    // ---- conv1 ----
    aggregate_kernel<<<2368, 256>>>(hP, eattr, We1, be1, eps1, aggP, N);
    gemm2_tc<<<gb, 256, SMEM2>>>(aggP, W11, b11, W12, b12, hP, N);

    // ---- conv2 ----
    aggregate_kernel<<<2368, 256>>>(hP, eattr, We2, be2, eps2, aggP, N);
    gemm2_tc<<<gb, 256, SMEM2>>>(aggP, W21, b21, W22, b22, out, N);
}

// round 6
// speedup vs baseline: 1.6576x; 1.1689x over previous
#include <cuda_runtime.h>
#include <cuda_fp16.h>
#include <cstdint>
#include <cstddef>

#define NMAX 200000
#define EMAX 600000
#define CH 128
#define LDP 136                      // padded row pitch in fp16 elems
#define PLANE_B (128 * LDP * 2)      // 34,816 bytes per 128x128 fp16 plane
#define PLANE_F4 (PLANE_B / 16)      // 2176 float4 per plane

// ---------------- scratch (device globals; no allocation allowed) ----------------
__device__ float g_h[(size_t)NMAX * CH];
__device__ float g_agg[(size_t)NMAX * CH];
__device__ int   g_src[EMAX];
__device__ int   g_dst[EMAX];
__device__ int2  g_epack[EMAX];
__device__ int   g_cnt[NMAX];
__device__ int   g_off[NMAX + 1];
__device__ int   g_cur[NMAX];
__device__ int   g_bsum[256];
__device__ int   g_bbase[256];
__device__ int   g_idx64;
__device__ float4 g_wplanes[5 * PLANE_F4];  // 5 weights, fp16-hi planes [k][n] LDP pitch

// ---------------- edge_index dtype sniffer ----------------
__global__ void detect_idx_kernel(const unsigned* __restrict__ p, int nwords)
{
    __shared__ unsigned s[32];
    unsigned v = 0;
    for (int i = threadIdx.x; i < 4096; i += blockDim.x) {
        int w = 2 * i + 1;
        if (w < nwords) v |= p[w];
    }
#pragma unroll
    for (int o = 16; o > 0; o >>= 1) v |= __shfl_xor_sync(0xffffffffu, v, o);
    int lane = threadIdx.x & 31, wid = threadIdx.x >> 5;
    if (lane == 0) s[wid] = v;
    __syncthreads();
    if (threadIdx.x == 0) {
        unsigned r = 0;
        int nw = (blockDim.x + 31) >> 5;
        for (int i = 0; i < nw; i++) r |= s[i];
        g_idx64 = (r == 0) ? 1 : 0;
    }
}

// ---------------- weight prep: fp16 round into padded [k][n] planes ----------------
__global__ void prep_weights(const float* __restrict__ W0, const float* __restrict__ W1,
                             const float* __restrict__ W2, const float* __restrict__ W3,
                             const float* __restrict__ W4)
{
    int idx = blockIdx.x * blockDim.x + threadIdx.x;
    if (idx >= 5 * 128 * LDP) return;
    int wi = idx / (128 * LDP);
    int e  = idx % (128 * LDP);
    int k = e / LDP, n = e % LDP;
    const float* W = (wi == 0) ? W0 : (wi == 1) ? W1 : (wi == 2) ? W2 : (wi == 3) ? W3 : W4;
    __half h = __float2half_rn(0.f);
    if (n < 128) h = __float2half_rn(__ldg(W + k * 128 + n));
    ((__half*)g_wplanes)[(size_t)wi * 128 * LDP + e] = h;
}

// ---------------- CSR build ----------------
__global__ void zero_counts_kernel(int N)
{
    int i = blockIdx.x * blockDim.x + threadIdx.x;
    if (i < N) g_cnt[i] = 0;
}

__global__ void convert_hist_kernel(const void* __restrict__ ei, int E)
{
    int i = blockIdx.x * blockDim.x + threadIdx.x;
    if (i >= E) return;
    int s, d;
    if (g_idx64) {
        const long long* p = (const long long*)ei;
        s = (int)p[i];
        d = (int)p[(size_t)E + i];
    } else {
        const int* p = (const int*)ei;
        s = p[i];
        d = p[E + i];
    }
    g_src[i] = s;
    g_dst[i] = d;
    atomicAdd(&g_cnt[d], 1);
}

__global__ void scan1_kernel(int N)
{
    __shared__ int s[32];
    int idx = blockIdx.x * 1024 + threadIdx.x;
    int v = (idx < N) ? g_cnt[idx] : 0;
    int t = v;
#pragma unroll
    for (int o = 16; o > 0; o >>= 1) t += __shfl_xor_sync(0xffffffffu, t, o);
    if ((threadIdx.x & 31) == 0) s[threadIdx.x >> 5] = t;
    __syncthreads();
    if (threadIdx.x == 0) {
        int r = 0;
        for (int i = 0; i < 32; i++) r += s[i];
        g_bsum[blockIdx.x] = r;
    }
}

__global__ void scan2_kernel(int nb, int N, int E)
{
    __shared__ int s[256];
    int t = threadIdx.x;
    int v = (t < nb) ? g_bsum[t] : 0;
    s[t] = v;
    __syncthreads();
#pragma unroll
    for (int o = 1; o < 256; o <<= 1) {
        int nv = s[t];
        if (t >= o) nv += s[t - o];
        __syncthreads();
        s[t] = nv;
        __syncthreads();
    }
    if (t < nb) g_bbase[t] = s[t] - v;
    if (t == 0) g_off[N] = E;
}

__global__ void scan3_kernel(int N)
{
    __shared__ int s[1024];
    int idx = blockIdx.x * 1024 + threadIdx.x;
    int t = threadIdx.x;
    int v = (idx < N) ? g_cnt[idx] : 0;
    s[t] = v;
    __syncthreads();
#pragma unroll
    for (int o = 1; o < 1024; o <<= 1) {
        int nv = s[t];
        if (t >= o) nv += s[t - o];
        __syncthreads();
        s[t] = nv;
        __syncthreads();
    }
    if (idx < N) {
        int excl = g_bbase[blockIdx.x] + s[t] - v;
        g_off[idx] = excl;
        g_cur[idx] = excl;
    }
}

__global__ void place_kernel(int E)
{
    int i = blockIdx.x * blockDim.x + threadIdx.x;
    if (i >= E) return;
    int d = g_dst[i];
    int p = atomicAdd(&g_cur[d], 1);
    g_epack[p] = make_int2(g_src[i], i);
}

// ---------------- CSR aggregation with software pipelining ----------------
// z[n] = (1+eps)*h[n] + sum_in relu(h[src] + eattr@We + be); one warp per node
__global__ __launch_bounds__(256)
void aggregate_kernel(const float* __restrict__ h, const float* __restrict__ eattr,
                      const float* __restrict__ We, const float* __restrict__ be,
                      const float* __restrict__ epsp,
                      float* __restrict__ z, int N)
{
    __shared__ float4 Wes[16][32];
    __shared__ float4 bes[32];
    int tid = threadIdx.x;
    for (int i = tid; i < 16 * 32; i += 256)
        ((float4*)Wes)[i] = ((const float4*)We)[i];
    if (tid < 32) bes[tid] = ((const float4*)be)[tid];
    __syncthreads();

    const float epc = 1.0f + __ldg(epsp);
    const int lane = tid & 31;
    int gw = (blockIdx.x * 256 + tid) >> 5;
    int nw = (gridDim.x * 256) >> 5;

    for (int n = gw; n < N; n += nw) {
        float4 hv = __ldg((const float4*)(h + (size_t)n * CH) + lane);
        float4 acc;
        acc.x = epc * hv.x;
        acc.y = epc * hv.y;
        acc.z = epc * hv.z;
        acc.w = epc * hv.w;

        const int p0 = __ldg(&g_off[n]);
        const int p1 = __ldg(&g_off[n + 1]);

        float4 sv, e0, e1, e2, e3;
        if (p0 < p1) {
            int2 ep = __ldg(&g_epack[p0]);
            sv = __ldg((const float4*)(h + (size_t)ep.x * CH) + lane);
            const float4* ea = ((const float4*)eattr) + (size_t)ep.y * 4;
            e0 = __ldg(ea + 0); e1 = __ldg(ea + 1); e2 = __ldg(ea + 2); e3 = __ldg(ea + 3);
        }
        for (int p = p0; p < p1; ++p) {
            float4 csv = sv, c0 = e0, c1 = e1, c2 = e2, c3 = e3;
            if (p + 1 < p1) {
                int2 ep = __ldg(&g_epack[p + 1]);
                sv = __ldg((const float4*)(h + (size_t)ep.x * CH) + lane);
                const float4* ea = ((const float4*)eattr) + (size_t)ep.y * 4;
                e0 = __ldg(ea + 0); e1 = __ldg(ea + 1); e2 = __ldg(ea + 2); e3 = __ldg(ea + 3);
            }
            float ev[16] = {c0.x, c0.y, c0.z, c0.w, c1.x, c1.y, c1.z, c1.w,
                            c2.x, c2.y, c2.z, c2.w, c3.x, c3.y, c3.z, c3.w};
            float4 m = bes[lane];
#pragma unroll
            for (int k = 0; k < 16; k++) {
                float4 w = Wes[k][lane];
                m.x += ev[k] * w.x;
                m.y += ev[k] * w.y;
                m.z += ev[k] * w.z;
                m.w += ev[k] * w.w;
            }
            acc.x += fmaxf(csv.x + m.x, 0.f);
            acc.y += fmaxf(csv.y + m.y, 0.f);
            acc.z += fmaxf(csv.z + m.z, 0.f);
            acc.w += fmaxf(csv.w + m.w, 0.f);
        }
        *(float4*)(z + (size_t)n * CH + lane * 4) = acc;
    }
}

// ---------------- fp16 tensor-core helpers ----------------
__device__ __forceinline__ uint32_t pack_h2_hi(float a, float b)
{
    __half ha = __float2half_rn(a), hb = __float2half_rn(b);
    return ((uint32_t)__half_as_ushort(hb) << 16) | __half_as_ushort(ha);
}
__device__ __forceinline__ uint32_t pack_h2_lo(float a, float b)
{
    __half ha = __float2half_rn(a), hb = __float2half_rn(b);
    __half la = __float2half_rn(a - __half2float(ha));
    __half lb = __float2half_rn(b - __half2float(hb));
    return ((uint32_t)__half_as_ushort(lb) << 16) | __half_as_ushort(la);
}

__device__ __forceinline__ void ldsm_x4(uint32_t* r, const void* p)
{
    uint32_t a = (uint32_t)__cvta_generic_to_shared(p);
    asm volatile("ldmatrix.sync.aligned.m8n8.x4.shared.b16 {%0,%1,%2,%3}, [%4];"
                 : "=r"(r[0]), "=r"(r[1]), "=r"(r[2]), "=r"(r[3]) : "r"(a));
}
__device__ __forceinline__ void ldsm_x4_t(uint32_t* r, const void* p)
{
    uint32_t a = (uint32_t)__cvta_generic_to_shared(p);
    asm volatile("ldmatrix.sync.aligned.m8n8.x4.trans.shared.b16 {%0,%1,%2,%3}, [%4];"
                 : "=r"(r[0]), "=r"(r[1]), "=r"(r[2]), "=r"(r[3]) : "r"(a));
}
__device__ __forceinline__ void mma_f16(float* c, const uint32_t* a, uint32_t b0, uint32_t b1)
{
    asm volatile("mma.sync.aligned.m16n8k16.row.col.f32.f16.f16.f32 "
                 "{%0,%1,%2,%3}, {%4,%5,%6,%7}, {%8,%9}, {%0,%1,%2,%3};"
                 : "+f"(c[0]), "+f"(c[1]), "+f"(c[2]), "+f"(c[3])
                 : "r"(a[0]), "r"(a[1]), "r"(a[2]), "r"(a[3]), "r"(b0), "r"(b1));
}
__device__ __forceinline__ void cp16(uint32_t dst, const void* src)
{
    asm volatile("cp.async.cg.shared.global [%0], [%1], 16;" :: "r"(dst), "l"(src) : "memory");
}
__device__ __forceinline__ void cp_commit_wait()
{
    asm volatile("cp.async.commit_group;\ncp.async.wait_group 0;" ::: "memory");
}

// stage A tile into fp16 hi/lo planes [r][k] LDP pitch
__device__ __forceinline__ void stage_a_f16(const float* __restrict__ A,
                                            __half* Ah, __half* Al,
                                            int tid, int row0, int M)
{
#pragma unroll
    for (int i = 0; i < 16; i++) {
        int idx = tid + i * 256;       // float4 idx 0..4095
        int r = idx >> 5, c4 = idx & 31;
        int g = row0 + r;
        float4 v = make_float4(0.f, 0.f, 0.f, 0.f);
        if (g < M) v = __ldg((const float4*)(A + (size_t)g * CH) + c4);
        *(uint2*)(Ah + r * LDP + c4 * 4) = make_uint2(pack_h2_hi(v.x, v.y), pack_h2_hi(v.z, v.w));
        *(uint2*)(Al + r * LDP + c4 * 4) = make_uint2(pack_h2_lo(v.x, v.y), pack_h2_lo(v.z, v.w));
    }
}

// 2-term fp16 pass, warp tile 32 rows x 64 cols (warps: 4 row-groups x 2 col-groups)
// C = (Ah + Al) @ Bh
__device__ __forceinline__ void mma_pass_f16(const __half* Ah, const __half* Al,
                                             const __half* Bh,
                                             int lane, int wr0, int wc0, float acc[2][8][4])
{
#pragma unroll
    for (int rg = 0; rg < 2; rg++)
#pragma unroll
        for (int t = 0; t < 8; t++)
#pragma unroll
            for (int j = 0; j < 4; j++) acc[rg][t][j] = 0.f;

    const int arow = wr0 + (lane & 15);
    const int aoff = (lane >> 4) << 3;

#pragma unroll
    for (int kc = 0; kc < 8; kc++) {
        const int kb = kc * 16;
        uint32_t ah0[4], ah1[4], al0[4], al1[4];
        ldsm_x4(ah0, Ah + (size_t)arow * LDP + kb + aoff);
        ldsm_x4(ah1, Ah + (size_t)(arow + 16) * LDP + kb + aoff);
        ldsm_x4(al0, Al + (size_t)arow * LDP + kb + aoff);
        ldsm_x4(al1, Al + (size_t)(arow + 16) * LDP + kb + aoff);
        const int brow = kb + (lane & 15);
#pragma unroll
        for (int ng = 0; ng < 4; ng++) {
            uint32_t b[4];
            ldsm_x4_t(b, Bh + (size_t)brow * LDP + wc0 + ng * 16 + aoff);
            mma_f16(acc[0][ng * 2],     ah0, b[0], b[1]);
            mma_f16(acc[0][ng * 2],     al0, b[0], b[1]);
            mma_f16(acc[0][ng * 2 + 1], ah0, b[2], b[3]);
            mma_f16(acc[0][ng * 2 + 1], al0, b[2], b[3]);
            mma_f16(acc[1][ng * 2],     ah1, b[0], b[1]);
            mma_f16(acc[1][ng * 2],     al1, b[0], b[1]);
            mma_f16(acc[1][ng * 2 + 1], ah1, b[2], b[3]);
            mma_f16(acc[1][ng * 2 + 1], al1, b[2], b[3]);
        }
    }
}

// ---------------- encoder GEMM: out = relu(A @ W + b) ----------------
// smem: Ah, Al, Wh planes + bias
#define G1_SMEM (3 * PLANE_B + 512)

__global__ __launch_bounds__(256)
void gemm_tc(const float* __restrict__ A, const float4* __restrict__ WhP,
             const float* __restrict__ bias, float* __restrict__ out, int M)
{
    extern __shared__ char sm[];
    __half* Ah = (__half*)sm;
    __half* Al = Ah + 128 * LDP;
    __half* Wh = Al + 128 * LDP;
    float* sbias = (float*)(sm + 3 * PLANE_B);
    uint32_t sbW = (uint32_t)__cvta_generic_to_shared(Wh);

    const int tid = threadIdx.x;
    const int warp = tid >> 5, lane = tid & 31;
    const int row0 = blockIdx.x * 128;

#pragma unroll
    for (int i = 0; i < 9; i++) {
        int j = tid + i * 256;
        if (j < PLANE_F4) cp16(sbW + j * 16, WhP + j);
    }
    if (tid < 128) sbias[tid] = __ldg(bias + tid);

    stage_a_f16(A, Ah, Al, tid, row0, M);
    cp_commit_wait();
    __syncthreads();

    const int wr0 = (warp >> 1) * 32;
    const int wc0 = (warp & 1) * 64;

    float acc[2][8][4];
    mma_pass_f16(Ah, Al, Wh, lane, wr0, wc0, acc);

    const int cb = (lane & 3) * 2;
#pragma unroll
    for (int rg = 0; rg < 2; rg++) {
        const int r = row0 + wr0 + rg * 16 + (lane >> 2);
#pragma unroll
        for (int t = 0; t < 8; t++) {
            const int n = wc0 + t * 8 + cb;
            const float b0 = sbias[n], b1 = sbias[n + 1];
            if (r < M) {
                float2 o;
                o.x = fmaxf(acc[rg][t][0] + b0, 0.f);
                o.y = fmaxf(acc[rg][t][1] + b1, 0.f);
                *(float2*)(out + (size_t)r * CH + n) = o;
            }
            if (r + 8 < M) {
                float2 o;
                o.x = fmaxf(acc[rg][t][2] + b0, 0.f);
                o.y = fmaxf(acc[rg][t][3] + b1, 0.f);
                *(float2*)(out + (size_t)(r + 8) * CH + n) = o;
            }
        }
    }
}

// ---------------- fused 2-layer MLP: out = relu(relu(A@W1+b1)@W2+b2) ----------------
// smem: Ah/Zh, Al/Zl, W1h, W2h planes + b1 + b2
#define G2_SMEM (4 * PLANE_B + 1024)

__global__ __launch_bounds__(256)
void gemm2_tc(const float* __restrict__ A,
              const float4* __restrict__ W1P, const float4* __restrict__ W2P,
              const float* __restrict__ b1, const float* __restrict__ b2,
              float* __restrict__ out, int M)
{
    extern __shared__ char sm[];
    __half* Ah  = (__half*)sm;
    __half* Al  = Ah + 128 * LDP;
    __half* W1h = Al + 128 * LDP;
    __half* W2h = W1h + 128 * LDP;
    float* sb1 = (float*)(sm + 4 * PLANE_B);
    float* sb2 = sb1 + 128;
    uint32_t sbW1 = (uint32_t)__cvta_generic_to_shared(W1h);
    uint32_t sbW2 = (uint32_t)__cvta_generic_to_shared(W2h);

    const int tid = threadIdx.x;
    const int warp = tid >> 5, lane = tid & 31;
    const int row0 = blockIdx.x * 128;

#pragma unroll
    for (int i = 0; i < 9; i++) {
        int j = tid + i * 256;
        if (j < PLANE_F4) {
            cp16(sbW1 + j * 16, W1P + j);
            cp16(sbW2 + j * 16, W2P + j);
        }
    }
    if (tid < 128) sb1[tid] = __ldg(b1 + tid);
    else           sb2[tid - 128] = __ldg(b2 + tid - 128);

    stage_a_f16(A, Ah, Al, tid, row0, M);
    cp_commit_wait();
    __syncthreads();

    const int wr0 = (warp >> 1) * 32;
    const int wc0 = (warp & 1) * 64;

    // ---- layer 1 ----
    float acc[2][8][4];
    mma_pass_f16(Ah, Al, W1h, lane, wr0, wc0, acc);
    __syncthreads();   // all warps done reading A planes

    // z = relu(acc + b1) -> split fp16 hi/lo back into A planes
    {
        const int cb = (lane & 3) * 2;
#pragma unroll
        for (int rg = 0; rg < 2; rg++) {
            const int rl = wr0 + rg * 16 + (lane >> 2);
#pragma unroll
            for (int t = 0; t < 8; t++) {
                const int n = wc0 + t * 8 + cb;
                const float b0 = sb1[n], b1v = sb1[n + 1];
                float z0 = fmaxf(acc[rg][t][0] + b0, 0.f);
                float z1 = fmaxf(acc[rg][t][1] + b1v, 0.f);
                float z2 = fmaxf(acc[rg][t][2] + b0, 0.f);
                float z3 = fmaxf(acc[rg][t][3] + b1v, 0.f);
                *(uint32_t*)(Ah + (size_t)rl * LDP + n)       = pack_h2_hi(z0, z1);
                *(uint32_t*)(Al + (size_t)rl * LDP + n)       = pack_h2_lo(z0, z1);
                *(uint32_t*)(Ah + (size_t)(rl + 8) * LDP + n) = pack_h2_hi(z2, z3);
                *(uint32_t*)(Al + (size_t)(rl + 8) * LDP + n) = pack_h2_lo(z2, z3);
            }
        }
    }
    __syncthreads();

    // ---- layer 2 ----
    mma_pass_f16(Ah, Al, W2h, lane, wr0, wc0, acc);

    const int cb = (lane & 3) * 2;
#pragma unroll
    for (int rg = 0; rg < 2; rg++) {
        const int r = row0 + wr0 + rg * 16 + (lane >> 2);
#pragma unroll
        for (int t = 0; t < 8; t++) {
            const int n = wc0 + t * 8 + cb;
            const float b0 = sb2[n], b1v = sb2[n + 1];
            if (r < M) {
                float2 o;
                o.x = fmaxf(acc[rg][t][0] + b0, 0.f);
                o.y = fmaxf(acc[rg][t][1] + b1v, 0.f);
                *(float2*)(out + (size_t)r * CH + n) = o;
            }
            if (r + 8 < M) {
                float2 o;
                o.x = fmaxf(acc[rg][t][2] + b0, 0.f);
                o.y = fmaxf(acc[rg][t][3] + b1v, 0.f);
                *(float2*)(out + (size_t)(r + 8) * CH + n) = o;
            }
        }
    }
}

// ---------------- launch ----------------
extern "C" void kernel_launch(void* const* d_in, const int* in_sizes, int n_in,
                              void* d_out, int out_size)
{
    const float* x     = (const float*)d_in[0];
    const void*  eidx  = d_in[1];
    const float* eattr = (const float*)d_in[2];
    const float* W_enc = (const float*)d_in[3];
    const float* b_enc = (const float*)d_in[4];
    const float* We1   = (const float*)d_in[5];
    const float* be1   = (const float*)d_in[6];
    const float* W11   = (const float*)d_in[7];
    const float* b11   = (const float*)d_in[8];
    const float* W12   = (const float*)d_in[9];
    const float* b12   = (const float*)d_in[10];
    const float* eps1  = (const float*)d_in[11];
    const float* We2   = (const float*)d_in[12];
    const float* be2   = (const float*)d_in[13];
    const float* W21   = (const float*)d_in[14];
    const float* b21   = (const float*)d_in[15];
    const float* W22   = (const float*)d_in[16];
    const float* b22   = (const float*)d_in[17];
    const float* eps2  = (const float*)d_in[18];

    const int N = in_sizes[0] / CH;
    const int E = in_sizes[2] / 16;
    float* out = (float*)d_out;

    float *hP, *aggP;
    float4* wpl;
    cudaGetSymbolAddress((void**)&hP, g_h);
    cudaGetSymbolAddress((void**)&aggP, g_agg);
    cudaGetSymbolAddress((void**)&wpl, g_wplanes);

    cudaFuncSetAttribute((const void*)gemm_tc,
                         cudaFuncAttributeMaxDynamicSharedMemorySize, G1_SMEM);
    cudaFuncSetAttribute((const void*)gemm2_tc,
                         cudaFuncAttributeMaxDynamicSharedMemorySize, G2_SMEM);

    const int nb = (N + 1023) / 1024;
    const int gb = (N + 127) / 128;

    // plane order: 0=W_enc, 1=W11, 2=W12, 3=W21, 4=W22
    detect_idx_kernel<<<1, 256>>>((const unsigned*)eidx, 2 * E);            // 1
    prep_weights<<<(5 * 128 * LDP + 255) / 256, 256>>>(W_enc, W11, W12, W21, W22); // 2
    zero_counts_kernel<<<nb, 1024>>>(N);                                    // 3
    gemm_tc<<<gb, 256, G1_SMEM>>>(x, wpl, b_enc, hP, N);                    // 4 (profiled)
    convert_hist_kernel<<<(E + 255) / 256, 256>>>(eidx, E);
    scan1_kernel<<<nb, 1024>>>(N);
    scan2_kernel<<<1, 256>>>(nb, N, E);
    scan3_kernel<<<nb, 1024>>>(N);
    place_kernel<<<(E + 255) / 256, 256>>>(E);

    // ---- conv1 ----
    aggregate_kernel<<<2368, 256>>>(hP, eattr, We1, be1, eps1, aggP, N);
    gemm2_tc<<<gb, 256, G2_SMEM>>>(aggP, wpl + 1 * PLANE_F4, wpl + 2 * PLANE_F4,
                                   b11, b12, hP, N);

    // ---- conv2 ----
    aggregate_kernel<<<2368, 256>>>(hP, eattr, We2, be2, eps2, aggP, N);
    gemm2_tc<<<gb, 256, G2_SMEM>>>(hP == nullptr ? aggP : aggP, wpl + 3 * PLANE_F4,
                                   wpl + 4 * PLANE_F4, b21, b22, out, N);
}

// round 7
// speedup vs baseline: 1.7271x; 1.0420x over previous
#include <cuda_runtime.h>
#include <cuda_fp16.h>
#include <cstdint>
#include <cstddef>

#define NMAX 200000
#define EMAX 600000
#define CH 128
#define LDP 136                      // padded row pitch in fp16 elems
#define PLANE_B (128 * LDP * 2)      // 34,816 bytes per 128x128 fp16 plane
#define PLANE_F4 (PLANE_B / 16)      // 2176 float4 per plane

// ---------------- scratch (device globals; no allocation allowed) ----------------
__device__ float g_h[(size_t)NMAX * CH];
__device__ float g_agg[(size_t)NMAX * CH];
__device__ int   g_src[EMAX];
__device__ int   g_dst[EMAX];
__device__ int2  g_epack[EMAX];      // (src, eid) in CSR order
__device__ __half g_ef[(size_t)2 * EMAX * CH];  // CSR-ordered edge features, both convs
__device__ int   g_cnt[NMAX];
__device__ int   g_off[NMAX + 1];
__device__ int   g_cur[NMAX];
__device__ int   g_bsum[256];
__device__ int   g_bbase[256];
__device__ int   g_idx64;
__device__ float4 g_wplanes[5 * PLANE_F4];  // 5 node-weights, fp16 planes [k][n]

// ---------------- edge_index dtype sniffer ----------------
__global__ void detect_idx_kernel(const unsigned* __restrict__ p, int nwords)
{
    __shared__ unsigned s[32];
    unsigned v = 0;
    for (int i = threadIdx.x; i < 4096; i += blockDim.x) {
        int w = 2 * i + 1;
        if (w < nwords) v |= p[w];
    }
#pragma unroll
    for (int o = 16; o > 0; o >>= 1) v |= __shfl_xor_sync(0xffffffffu, v, o);
    int lane = threadIdx.x & 31, wid = threadIdx.x >> 5;
    if (lane == 0) s[wid] = v;
    __syncthreads();
    if (threadIdx.x == 0) {
        unsigned r = 0;
        int nw = (blockDim.x + 31) >> 5;
        for (int i = 0; i < nw; i++) r |= s[i];
        g_idx64 = (r == 0) ? 1 : 0;
    }
}

// ---------------- weight prep: fp16 round into padded [k][n] planes ----------------
__global__ void prep_weights(const float* __restrict__ W0, const float* __restrict__ W1,
                             const float* __restrict__ W2, const float* __restrict__ W3,
                             const float* __restrict__ W4)
{
    int idx = blockIdx.x * blockDim.x + threadIdx.x;
    if (idx >= 5 * 128 * LDP) return;
    int wi = idx / (128 * LDP);
    int e  = idx % (128 * LDP);
    int k = e / LDP, n = e % LDP;
    const float* W = (wi == 0) ? W0 : (wi == 1) ? W1 : (wi == 2) ? W2 : (wi == 3) ? W3 : W4;
    __half h = __float2half_rn(0.f);
    if (n < 128) h = __float2half_rn(__ldg(W + k * 128 + n));
    ((__half*)g_wplanes)[(size_t)wi * 128 * LDP + e] = h;
}

// ---------------- CSR build ----------------
__global__ void zero_counts_kernel(int N)
{
    int i = blockIdx.x * blockDim.x + threadIdx.x;
    if (i < N) g_cnt[i] = 0;
}

__global__ void convert_hist_kernel(const void* __restrict__ ei, int E)
{
    int i = blockIdx.x * blockDim.x + threadIdx.x;
    if (i >= E) return;
    int s, d;
    if (g_idx64) {
        const long long* p = (const long long*)ei;
        s = (int)p[i];
        d = (int)p[(size_t)E + i];
    } else {
        const int* p = (const int*)ei;
        s = p[i];
        d = p[E + i];
    }
    g_src[i] = s;
    g_dst[i] = d;
    atomicAdd(&g_cnt[d], 1);
}

__global__ void scan1_kernel(int N)
{
    __shared__ int s[32];
    int idx = blockIdx.x * 1024 + threadIdx.x;
    int v = (idx < N) ? g_cnt[idx] : 0;
    int t = v;
#pragma unroll
    for (int o = 16; o > 0; o >>= 1) t += __shfl_xor_sync(0xffffffffu, t, o);
    if ((threadIdx.x & 31) == 0) s[threadIdx.x >> 5] = t;
    __syncthreads();
    if (threadIdx.x == 0) {
        int r = 0;
        for (int i = 0; i < 32; i++) r += s[i];
        g_bsum[blockIdx.x] = r;
    }
}

__global__ void scan2_kernel(int nb, int N, int E)
{
    __shared__ int s[256];
    int t = threadIdx.x;
    int v = (t < nb) ? g_bsum[t] : 0;
    s[t] = v;
    __syncthreads();
#pragma unroll
    for (int o = 1; o < 256; o <<= 1) {
        int nv = s[t];
        if (t >= o) nv += s[t - o];
        __syncthreads();
        s[t] = nv;
        __syncthreads();
    }
    if (t < nb) g_bbase[t] = s[t] - v;
    if (t == 0) g_off[N] = E;
}

__global__ void scan3_kernel(int N)
{
    __shared__ int s[1024];
    int idx = blockIdx.x * 1024 + threadIdx.x;
    int t = threadIdx.x;
    int v = (idx < N) ? g_cnt[idx] : 0;
    s[t] = v;
    __syncthreads();
#pragma unroll
    for (int o = 1; o < 1024; o <<= 1) {
        int nv = s[t];
        if (t >= o) nv += s[t - o];
        __syncthreads();
        s[t] = nv;
        __syncthreads();
    }
    if (idx < N) {
        int excl = g_bbase[blockIdx.x] + s[t] - v;
        g_off[idx] = excl;
        g_cur[idx] = excl;
    }
}

__global__ void place_kernel(int E)
{
    int i = blockIdx.x * blockDim.x + threadIdx.x;
    if (i >= E) return;
    int d = g_dst[i];
    int p = atomicAdd(&g_cur[d], 1);
    g_epack[p] = make_int2(g_src[i], i);
}

// ---------------- fp16 helpers ----------------
__device__ __forceinline__ uint32_t pack_h2_hi(float a, float b)
{
    __half ha = __float2half_rn(a), hb = __float2half_rn(b);
    return ((uint32_t)__half_as_ushort(hb) << 16) | __half_as_ushort(ha);
}
__device__ __forceinline__ uint32_t pack_h2_lo(float a, float b)
{
    __half ha = __float2half_rn(a), hb = __float2half_rn(b);
    __half la = __float2half_rn(a - __half2float(ha));
    __half lb = __float2half_rn(b - __half2float(hb));
    return ((uint32_t)__half_as_ushort(lb) << 16) | __half_as_ushort(la);
}
__device__ __forceinline__ void ldsm_x4(uint32_t* r, const void* p)
{
    uint32_t a = (uint32_t)__cvta_generic_to_shared(p);
    asm volatile("ldmatrix.sync.aligned.m8n8.x4.shared.b16 {%0,%1,%2,%3}, [%4];"
                 : "=r"(r[0]), "=r"(r[1]), "=r"(r[2]), "=r"(r[3]) : "r"(a));
}
__device__ __forceinline__ void ldsm_x4_t(uint32_t* r, const void* p)
{
    uint32_t a = (uint32_t)__cvta_generic_to_shared(p);
    asm volatile("ldmatrix.sync.aligned.m8n8.x4.trans.shared.b16 {%0,%1,%2,%3}, [%4];"
                 : "=r"(r[0]), "=r"(r[1]), "=r"(r[2]), "=r"(r[3]) : "r"(a));
}
__device__ __forceinline__ void mma_f16(float* c, const uint32_t* a, uint32_t b0, uint32_t b1)
{
    asm volatile("mma.sync.aligned.m16n8k16.row.col.f32.f16.f16.f32 "
                 "{%0,%1,%2,%3}, {%4,%5,%6,%7}, {%8,%9}, {%0,%1,%2,%3};"
                 : "+f"(c[0]), "+f"(c[1]), "+f"(c[2]), "+f"(c[3])
                 : "r"(a[0]), "r"(a[1]), "r"(a[2]), "r"(a[3]), "r"(b0), "r"(b1));
}
__device__ __forceinline__ void cp16(uint32_t dst, const void* src)
{
    asm volatile("cp.async.cg.shared.global [%0], [%1], 16;" :: "r"(dst), "l"(src) : "memory");
}
__device__ __forceinline__ void cp_commit_wait()
{
    asm volatile("cp.async.commit_group;\ncp.async.wait_group 0;" ::: "memory");
}

// ---------------- edge-feature GEMM (both convs): ef[p] = eattr[eid(p)]@We + be ----------------
// CTA: 128 CSR slots; gather eattr rows, 3-term split fp16 MMA, store fp16 ef in CSR order.
#define EG_SMEM (2 * PLANE_B + 4 * (16 * LDP * 2) + 1024)

__global__ __launch_bounds__(256, 2)
void edgegemm_kernel(const float* __restrict__ eattr,
                     const float* __restrict__ We1, const float* __restrict__ be1,
                     const float* __restrict__ We2, const float* __restrict__ be2,
                     int E)
{
    extern __shared__ char sm[];
    __half* Ah  = (__half*)sm;                 // [128][LDP], cols 0..15 used
    __half* Al  = Ah + 128 * LDP;
    __half* W1h = Al + 128 * LDP;              // [16][LDP]
    __half* W1l = W1h + 16 * LDP;
    __half* W2h = W1l + 16 * LDP;
    __half* W2l = W2h + 16 * LDP;
    float* sb1 = (float*)(W2l + 16 * LDP);
    float* sb2 = sb1 + 128;

    const int tid = threadIdx.x;
    const int warp = tid >> 5, lane = tid & 31;
    const int p0 = blockIdx.x * 128;

    // stage We planes (split) + biases
    for (int i = tid; i < 2 * 2048; i += 256) {
        int conv = i >> 11, e = i & 2047;
        int k = e >> 7, n = e & 127;
        const float* W = conv ? We2 : We1;
        float v = __ldg(W + e);
        __half h = __float2half_rn(v);
        __half l = __float2half_rn(v - __half2float(h));
        (conv ? W2h : W1h)[k * LDP + n] = h;
        (conv ? W2l : W1l)[k * LDP + n] = l;
    }
    if (tid < 128) sb1[tid] = __ldg(be1 + tid);
    else           sb2[tid - 128] = __ldg(be2 + tid - 128);

    // gather + split-convert 128 eattr rows (2 threads per row)
    {
        int rowp = tid >> 1;
        int hoff = (tid & 1) * 8;
        int p = p0 + rowp;
        float4 v0 = make_float4(0.f, 0.f, 0.f, 0.f), v1 = v0;
        if (p < E) {
            int eid = __ldg(&g_epack[p]).y;
            const float4* ea = (const float4*)eattr + (size_t)eid * 4 + (tid & 1) * 2;
            v0 = __ldg(ea);
            v1 = __ldg(ea + 1);
        }
        *(uint2*)(Ah + rowp * LDP + hoff)     = make_uint2(pack_h2_hi(v0.x, v0.y), pack_h2_hi(v0.z, v0.w));
        *(uint2*)(Ah + rowp * LDP + hoff + 4) = make_uint2(pack_h2_hi(v1.x, v1.y), pack_h2_hi(v1.z, v1.w));
        *(uint2*)(Al + rowp * LDP + hoff)     = make_uint2(pack_h2_lo(v0.x, v0.y), pack_h2_lo(v0.z, v0.w));
        *(uint2*)(Al + rowp * LDP + hoff + 4) = make_uint2(pack_h2_lo(v1.x, v1.y), pack_h2_lo(v1.z, v1.w));
    }
    __syncthreads();

    const int wr0 = warp * 16;
    const int arow = wr0 + (lane & 15);
    const int aoff = (lane >> 4) << 3;

    uint32_t ah[4], al[4];
    ldsm_x4(ah, Ah + arow * LDP + aoff);
    ldsm_x4(al, Al + arow * LDP + aoff);

    const int brow = (lane & 15);
    const int cb = (lane & 3) * 2;
    const int r0 = p0 + wr0 + (lane >> 2);

#pragma unroll
    for (int conv = 0; conv < 2; conv++) {
        const __half* Wh = conv ? W2h : W1h;
        const __half* Wl = conv ? W2l : W1l;
        const float* sb = conv ? sb2 : sb1;
        __half* efo = g_ef + (size_t)conv * EMAX * CH;
#pragma unroll
        for (int nh = 0; nh < 2; nh++) {
            float acc[8][4];
#pragma unroll
            for (int t = 0; t < 8; t++)
#pragma unroll
                for (int j = 0; j < 4; j++) acc[t][j] = 0.f;
#pragma unroll
            for (int ng = 0; ng < 4; ng++) {
                const int n0 = nh * 64 + ng * 16;
                uint32_t bh[4], bl[4];
                ldsm_x4_t(bh, Wh + brow * LDP + n0 + aoff);
                ldsm_x4_t(bl, Wl + brow * LDP + n0 + aoff);
                mma_f16(acc[ng * 2],     ah, bh[0], bh[1]);
                mma_f16(acc[ng * 2],     al, bh[0], bh[1]);
                mma_f16(acc[ng * 2],     ah, bl[0], bl[1]);
                mma_f16(acc[ng * 2 + 1], ah, bh[2], bh[3]);
                mma_f16(acc[ng * 2 + 1], al, bh[2], bh[3]);
                mma_f16(acc[ng * 2 + 1], ah, bl[2], bl[3]);
            }
#pragma unroll
            for (int t = 0; t < 8; t++) {
                const int n = nh * 64 + t * 8 + cb;
                const float b0 = sb[n], b1 = sb[n + 1];
                if (r0 < E)
                    *(uint32_t*)(efo + (size_t)r0 * CH + n) =
                        pack_h2_hi(acc[t][0] + b0, acc[t][1] + b1);
                if (r0 + 8 < E)
                    *(uint32_t*)(efo + (size_t)(r0 + 8) * CH + n) =
                        pack_h2_hi(acc[t][2] + b0, acc[t][3] + b1);
            }
        }
    }
}

// ---------------- lightweight CSR aggregation ----------------
// z[n] = (1+eps)*h[n] + sum_in relu(h[src] + ef[p]); one warp per node
__global__ __launch_bounds__(256)
void aggregate_kernel(const float* __restrict__ h, const __half* __restrict__ ef,
                      const float* __restrict__ epsp,
                      float* __restrict__ z, int N)
{
    const float epc = 1.0f + __ldg(epsp);
    const int tid = threadIdx.x;
    const int lane = tid & 31;
    int gw = (blockIdx.x * 256 + tid) >> 5;
    int nw = (gridDim.x * 256) >> 5;

    for (int n = gw; n < N; n += nw) {
        float4 hv = __ldg((const float4*)(h + (size_t)n * CH) + lane);
        float4 acc;
        acc.x = epc * hv.x;
        acc.y = epc * hv.y;
        acc.z = epc * hv.z;
        acc.w = epc * hv.w;

        const int p0 = __ldg(&g_off[n]);
        const int p1 = __ldg(&g_off[n + 1]);

        float4 sv;
        uint2 eu;
        if (p0 < p1) {
            int s = __ldg(&g_epack[p0]).x;
            sv = __ldg((const float4*)(h + (size_t)s * CH) + lane);
            eu = __ldg((const uint2*)(ef + (size_t)p0 * CH) + lane);
        }
        for (int p = p0; p < p1; ++p) {
            float4 csv = sv;
            uint2 ceu = eu;
            if (p + 1 < p1) {
                int s = __ldg(&g_epack[p + 1]).x;
                sv = __ldg((const float4*)(h + (size_t)s * CH) + lane);
                eu = __ldg((const uint2*)(ef + (size_t)(p + 1) * CH) + lane);
            }
            float2 f01 = __half22float2(*(__half2*)&ceu.x);
            float2 f23 = __half22float2(*(__half2*)&ceu.y);
            acc.x += fmaxf(csv.x + f01.x, 0.f);
            acc.y += fmaxf(csv.y + f01.y, 0.f);
            acc.z += fmaxf(csv.z + f23.x, 0.f);
            acc.w += fmaxf(csv.w + f23.y, 0.f);
        }
        *(float4*)(z + (size_t)n * CH + lane * 4) = acc;
    }
}

// stage A tile into fp16 hi/lo planes [r][k] LDP pitch
__device__ __forceinline__ void stage_a_f16(const float* __restrict__ A,
                                            __half* Ah, __half* Al,
                                            int tid, int row0, int M)
{
#pragma unroll
    for (int i = 0; i < 16; i++) {
        int idx = tid + i * 256;
        int r = idx >> 5, c4 = idx & 31;
        int g = row0 + r;
        float4 v = make_float4(0.f, 0.f, 0.f, 0.f);
        if (g < M) v = __ldg((const float4*)(A + (size_t)g * CH) + c4);
        *(uint2*)(Ah + r * LDP + c4 * 4) = make_uint2(pack_h2_hi(v.x, v.y), pack_h2_hi(v.z, v.w));
        *(uint2*)(Al + r * LDP + c4 * 4) = make_uint2(pack_h2_lo(v.x, v.y), pack_h2_lo(v.z, v.w));
    }
}

// 2-term fp16 pass, warp tile 32 rows x 64 cols
__device__ __forceinline__ void mma_pass_f16(const __half* Ah, const __half* Al,
                                             const __half* Bh,
                                             int lane, int wr0, int wc0, float acc[2][8][4])
{
#pragma unroll
    for (int rg = 0; rg < 2; rg++)
#pragma unroll
        for (int t = 0; t < 8; t++)
#pragma unroll
            for (int j = 0; j < 4; j++) acc[rg][t][j] = 0.f;

    const int arow = wr0 + (lane & 15);
    const int aoff = (lane >> 4) << 3;

#pragma unroll
    for (int kc = 0; kc < 8; kc++) {
        const int kb = kc * 16;
        uint32_t ah0[4], ah1[4], al0[4], al1[4];
        ldsm_x4(ah0, Ah + (size_t)arow * LDP + kb + aoff);
        ldsm_x4(ah1, Ah + (size_t)(arow + 16) * LDP + kb + aoff);
        ldsm_x4(al0, Al + (size_t)arow * LDP + kb + aoff);
        ldsm_x4(al1, Al + (size_t)(arow + 16) * LDP + kb + aoff);
        const int brow = kb + (lane & 15);
#pragma unroll
        for (int ng = 0; ng < 4; ng++) {
            uint32_t b[4];
            ldsm_x4_t(b, Bh + (size_t)brow * LDP + wc0 + ng * 16 + aoff);
            mma_f16(acc[0][ng * 2],     ah0, b[0], b[1]);
            mma_f16(acc[0][ng * 2],     al0, b[0], b[1]);
            mma_f16(acc[0][ng * 2 + 1], ah0, b[2], b[3]);
            mma_f16(acc[0][ng * 2 + 1], al0, b[2], b[3]);
            mma_f16(acc[1][ng * 2],     ah1, b[0], b[1]);
            mma_f16(acc[1][ng * 2],     al1, b[0], b[1]);
            mma_f16(acc[1][ng * 2 + 1], ah1, b[2], b[3]);
            mma_f16(acc[1][ng * 2 + 1], al1, b[2], b[3]);
        }
    }
}

// ---------------- encoder GEMM: out = relu(A @ W + b) ----------------
#define G1_SMEM (3 * PLANE_B + 512)

__global__ __launch_bounds__(256)
void gemm_tc(const float* __restrict__ A, const float4* __restrict__ WhP,
             const float* __restrict__ bias, float* __restrict__ out, int M)
{
    extern __shared__ char sm[];
    __half* Ah = (__half*)sm;
    __half* Al = Ah + 128 * LDP;
    __half* Wh = Al + 128 * LDP;
    float* sbias = (float*)(sm + 3 * PLANE_B);
    uint32_t sbW = (uint32_t)__cvta_generic_to_shared(Wh);

    const int tid = threadIdx.x;
    const int warp = tid >> 5, lane = tid & 31;
    const int row0 = blockIdx.x * 128;

#pragma unroll
    for (int i = 0; i < 9; i++) {
        int j = tid + i * 256;
        if (j < PLANE_F4) cp16(sbW + j * 16, WhP + j);
    }
    if (tid < 128) sbias[tid] = __ldg(bias + tid);

    stage_a_f16(A, Ah, Al, tid, row0, M);
    cp_commit_wait();
    __syncthreads();

    const int wr0 = (warp >> 1) * 32;
    const int wc0 = (warp & 1) * 64;

    float acc[2][8][4];
    mma_pass_f16(Ah, Al, Wh, lane, wr0, wc0, acc);

    const int cb = (lane & 3) * 2;
#pragma unroll
    for (int rg = 0; rg < 2; rg++) {
        const int r = row0 + wr0 + rg * 16 + (lane >> 2);
#pragma unroll
        for (int t = 0; t < 8; t++) {
            const int n = wc0 + t * 8 + cb;
            const float b0 = sbias[n], b1 = sbias[n + 1];
            if (r < M) {
                float2 o;
                o.x = fmaxf(acc[rg][t][0] + b0, 0.f);
                o.y = fmaxf(acc[rg][t][1] + b1, 0.f);
                *(float2*)(out + (size_t)r * CH + n) = o;
            }
            if (r + 8 < M) {
                float2 o;
                o.x = fmaxf(acc[rg][t][2] + b0, 0.f);
                o.y = fmaxf(acc[rg][t][3] + b1, 0.f);
                *(float2*)(out + (size_t)(r + 8) * CH + n) = o;
            }
        }
    }
}

// ---------------- fused 2-layer MLP: out = relu(relu(A@W1+b1)@W2+b2) ----------------
#define G2_SMEM (4 * PLANE_B + 1024)

__global__ __launch_bounds__(256)
void gemm2_tc(const float* __restrict__ A,
              const float4* __restrict__ W1P, const float4* __restrict__ W2P,
              const float* __restrict__ b1, const float* __restrict__ b2,
              float* __restrict__ out, int M)
{
    extern __shared__ char sm[];
    __half* Ah  = (__half*)sm;
    __half* Al  = Ah + 128 * LDP;
    __half* W1h = Al + 128 * LDP;
    __half* W2h = W1h + 128 * LDP;
    float* sb1 = (float*)(sm + 4 * PLANE_B);
    float* sb2 = sb1 + 128;
    uint32_t sbW1 = (uint32_t)__cvta_generic_to_shared(W1h);
    uint32_t sbW2 = (uint32_t)__cvta_generic_to_shared(W2h);

    const int tid = threadIdx.x;
    const int warp = tid >> 5, lane = tid & 31;
    const int row0 = blockIdx.x * 128;

#pragma unroll
    for (int i = 0; i < 9; i++) {
        int j = tid + i * 256;
        if (j < PLANE_F4) {
            cp16(sbW1 + j * 16, W1P + j);
            cp16(sbW2 + j * 16, W2P + j);
        }
    }
    if (tid < 128) sb1[tid] = __ldg(b1 + tid);
    else           sb2[tid - 128] = __ldg(b2 + tid - 128);

    stage_a_f16(A, Ah, Al, tid, row0, M);
    cp_commit_wait();
    __syncthreads();

    const int wr0 = (warp >> 1) * 32;
    const int wc0 = (warp & 1) * 64;

    float acc[2][8][4];
    mma_pass_f16(Ah, Al, W1h, lane, wr0, wc0, acc);
    __syncthreads();

    {
        const int cb = (lane & 3) * 2;
#pragma unroll
        for (int rg = 0; rg < 2; rg++) {
            const int rl = wr0 + rg * 16 + (lane >> 2);
#pragma unroll
            for (int t = 0; t < 8; t++) {
                const int n = wc0 + t * 8 + cb;
                const float b0 = sb1[n], b1v = sb1[n + 1];
                float z0 = fmaxf(acc[rg][t][0] + b0, 0.f);
                float z1 = fmaxf(acc[rg][t][1] + b1v, 0.f);
                float z2 = fmaxf(acc[rg][t][2] + b0, 0.f);
                float z3 = fmaxf(acc[rg][t][3] + b1v, 0.f);
                *(uint32_t*)(Ah + (size_t)rl * LDP + n)       = pack_h2_hi(z0, z1);
                *(uint32_t*)(Al + (size_t)rl * LDP + n)       = pack_h2_lo(z0, z1);
                *(uint32_t*)(Ah + (size_t)(rl + 8) * LDP + n) = pack_h2_hi(z2, z3);
                *(uint32_t*)(Al + (size_t)(rl + 8) * LDP + n) = pack_h2_lo(z2, z3);
            }
        }
    }
    __syncthreads();

    mma_pass_f16(Ah, Al, W2h, lane, wr0, wc0, acc);

    const int cb = (lane & 3) * 2;
#pragma unroll
    for (int rg = 0; rg < 2; rg++) {
        const int r = row0 + wr0 + rg * 16 + (lane >> 2);
#pragma unroll
        for (int t = 0; t < 8; t++) {
            const int n = wc0 + t * 8 + cb;
            const float b0 = sb2[n], b1v = sb2[n + 1];
            if (r < M) {
                float2 o;
                o.x = fmaxf(acc[rg][t][0] + b0, 0.f);
                o.y = fmaxf(acc[rg][t][1] + b1v, 0.f);
                *(float2*)(out + (size_t)r * CH + n) = o;
            }
            if (r + 8 < M) {
                float2 o;
                o.x = fmaxf(acc[rg][t][2] + b0, 0.f);
                o.y = fmaxf(acc[rg][t][3] + b1v, 0.f);
                *(float2*)(out + (size_t)(r + 8) * CH + n) = o;
            }
        }
    }
}

// ---------------- launch ----------------
extern "C" void kernel_launch(void* const* d_in, const int* in_sizes, int n_in,
                              void* d_out, int out_size)
{
    const float* x     = (const float*)d_in[0];
    const void*  eidx  = d_in[1];
    const float* eattr = (const float*)d_in[2];
    const float* W_enc = (const float*)d_in[3];
    const float* b_enc = (const float*)d_in[4];
    const float* We1   = (const float*)d_in[5];
    const float* be1   = (const float*)d_in[6];
    const float* W11   = (const float*)d_in[7];
    const float* b11   = (const float*)d_in[8];
    const float* W12   = (const float*)d_in[9];
    const float* b12   = (const float*)d_in[10];
    const float* eps1  = (const float*)d_in[11];
    const float* We2   = (const float*)d_in[12];
    const float* be2   = (const float*)d_in[13];
    const float* W21   = (const float*)d_in[14];
    const float* b21   = (const float*)d_in[15];
    const float* W22   = (const float*)d_in[16];
    const float* b22   = (const float*)d_in[17];
    const float* eps2  = (const float*)d_in[18];

    const int N = in_sizes[0] / CH;
    const int E = in_sizes[2] / 16;
    float* out = (float*)d_out;

    float *hP, *aggP;
    float4* wpl;
    __half* efP;
    cudaGetSymbolAddress((void**)&hP, g_h);
    cudaGetSymbolAddress((void**)&aggP, g_agg);
    cudaGetSymbolAddress((void**)&wpl, g_wplanes);
    cudaGetSymbolAddress((void**)&efP, g_ef);

    cudaFuncSetAttribute((const void*)gemm_tc,
                         cudaFuncAttributeMaxDynamicSharedMemorySize, G1_SMEM);
    cudaFuncSetAttribute((const void*)gemm2_tc,
                         cudaFuncAttributeMaxDynamicSharedMemorySize, G2_SMEM);
    cudaFuncSetAttribute((const void*)edgegemm_kernel,
                         cudaFuncAttributeMaxDynamicSharedMemorySize, EG_SMEM);

    const int nb = (N + 1023) / 1024;
    const int gb = (N + 127) / 128;

    detect_idx_kernel<<<1, 256>>>((const unsigned*)eidx, 2 * E);                    // 1
    prep_weights<<<(5 * 128 * LDP + 255) / 256, 256>>>(W_enc, W11, W12, W21, W22);  // 2
    zero_counts_kernel<<<nb, 1024>>>(N);                                            // 3
    gemm_tc<<<gb, 256, G1_SMEM>>>(x, wpl, b_enc, hP, N);                            // 4 (profiled)
    convert_hist_kernel<<<(E + 255) / 256, 256>>>(eidx, E);
    scan1_kernel<<<nb, 1024>>>(N);
    scan2_kernel<<<1, 256>>>(nb, N, E);
    scan3_kernel<<<nb, 1024>>>(N);
    place_kernel<<<(E + 255) / 256, 256>>>(E);
    edgegemm_kernel<<<(E + 127) / 128, 256, EG_SMEM>>>(eattr, We1, be1, We2, be2, E);

    // ---- conv1 ----
    aggregate_kernel<<<2368, 256>>>(hP, efP, eps1, aggP, N);
    gemm2_tc<<<gb, 256, G2_SMEM>>>(aggP, wpl + 1 * PLANE_F4, wpl + 2 * PLANE_F4,
                                   b11, b12, hP, N);

    // ---- conv2 ----
    aggregate_kernel<<<2368, 256>>>(hP, efP + (size_t)EMAX * CH, eps2, aggP, N);
    gemm2_tc<<<gb, 256, G2_SMEM>>>(aggP, wpl + 3 * PLANE_F4, wpl + 4 * PLANE_F4,
                                   b21, b22, out, N);
}

// round 8
// speedup vs baseline: 1.7740x; 1.0272x over previous
#include <cuda_runtime.h>
#include <cuda_fp16.h>
#include <cstdint>
#include <cstddef>

#define NMAX 200000
#define EMAX 600000
#define CH 128
#define LDP 136                      // padded row pitch in fp16 elems
#define PLANE_B (128 * LDP * 2)      // 34,816 bytes per 128x128 fp16 plane
#define PLANE_F4 (PLANE_B / 16)      // 2176 float4 per plane

// ---------------- scratch (device globals; no allocation allowed) ----------------
__device__ __half g_hh[(size_t)NMAX * CH];   // h hi plane (fp16)
__device__ __half g_hl[(size_t)NMAX * CH];   // h lo plane (fp16 residual)
__device__ float g_agg[(size_t)NMAX * CH];
__device__ int   g_src[EMAX];
__device__ int   g_dst[EMAX];
__device__ int2  g_epack[EMAX];              // (src, eid) in CSR order
__device__ __half g_ef[(size_t)2 * EMAX * CH];  // CSR-ordered edge features, both convs
__device__ int   g_cnt[NMAX];
__device__ int   g_off[NMAX + 1];
__device__ int   g_cur[NMAX];
__device__ int   g_bsum[256];
__device__ int   g_bbase[256];
__device__ int   g_idx64;
__device__ float4 g_wplanes[5 * PLANE_F4];   // 5 node-weights, fp16 planes [k][n]

// ---------------- edge_index dtype sniffer ----------------
__global__ void detect_idx_kernel(const unsigned* __restrict__ p, int nwords)
{
    __shared__ unsigned s[32];
    unsigned v = 0;
    for (int i = threadIdx.x; i < 4096; i += blockDim.x) {
        int w = 2 * i + 1;
        if (w < nwords) v |= p[w];
    }
#pragma unroll
    for (int o = 16; o > 0; o >>= 1) v |= __shfl_xor_sync(0xffffffffu, v, o);
    int lane = threadIdx.x & 31, wid = threadIdx.x >> 5;
    if (lane == 0) s[wid] = v;
    __syncthreads();
    if (threadIdx.x == 0) {
        unsigned r = 0;
        int nw = (blockDim.x + 31) >> 5;
        for (int i = 0; i < nw; i++) r |= s[i];
        g_idx64 = (r == 0) ? 1 : 0;
    }
}

// ---------------- weight prep: fp16 round into padded [k][n] planes ----------------
__global__ void prep_weights(const float* __restrict__ W0, const float* __restrict__ W1,
                             const float* __restrict__ W2, const float* __restrict__ W3,
                             const float* __restrict__ W4)
{
    int idx = blockIdx.x * blockDim.x + threadIdx.x;
    if (idx >= 5 * 128 * LDP) return;
    int wi = idx / (128 * LDP);
    int e  = idx % (128 * LDP);
    int k = e / LDP, n = e % LDP;
    const float* W = (wi == 0) ? W0 : (wi == 1) ? W1 : (wi == 2) ? W2 : (wi == 3) ? W3 : W4;
    __half h = __float2half_rn(0.f);
    if (n < 128) h = __float2half_rn(__ldg(W + k * 128 + n));
    ((__half*)g_wplanes)[(size_t)wi * 128 * LDP + e] = h;
}

// ---------------- CSR build ----------------
__global__ void zero_counts_kernel(int N)
{
    int i = blockIdx.x * blockDim.x + threadIdx.x;
    if (i < N) g_cnt[i] = 0;
}

__global__ void convert_hist_kernel(const void* __restrict__ ei, int E)
{
    int i = blockIdx.x * blockDim.x + threadIdx.x;
    if (i >= E) return;
    int s, d;
    if (g_idx64) {
        const long long* p = (const long long*)ei;
        s = (int)p[i];
        d = (int)p[(size_t)E + i];
    } else {
        const int* p = (const int*)ei;
        s = p[i];
        d = p[E + i];
    }
    g_src[i] = s;
    g_dst[i] = d;
    atomicAdd(&g_cnt[d], 1);
}

__global__ void scan1_kernel(int N)
{
    __shared__ int s[32];
    int idx = blockIdx.x * 1024 + threadIdx.x;
    int v = (idx < N) ? g_cnt[idx] : 0;
    int t = v;
#pragma unroll
    for (int o = 16; o > 0; o >>= 1) t += __shfl_xor_sync(0xffffffffu, t, o);
    if ((threadIdx.x & 31) == 0) s[threadIdx.x >> 5] = t;
    __syncthreads();
    if (threadIdx.x == 0) {
        int r = 0;
        for (int i = 0; i < 32; i++) r += s[i];
        g_bsum[blockIdx.x] = r;
    }
}

__global__ void scan2_kernel(int nb, int N, int E)
{
    __shared__ int s[256];
    int t = threadIdx.x;
    int v = (t < nb) ? g_bsum[t] : 0;
    s[t] = v;
    __syncthreads();
#pragma unroll
    for (int o = 1; o < 256; o <<= 1) {
        int nv = s[t];
        if (t >= o) nv += s[t - o];
        __syncthreads();
        s[t] = nv;
        __syncthreads();
    }
    if (t < nb) g_bbase[t] = s[t] - v;
    if (t == 0) g_off[N] = E;
}

__global__ void scan3_kernel(int N)
{
    __shared__ int s[1024];
    int idx = blockIdx.x * 1024 + threadIdx.x;
    int t = threadIdx.x;
    int v = (idx < N) ? g_cnt[idx] : 0;
    s[t] = v;
    __syncthreads();
#pragma unroll
    for (int o = 1; o < 1024; o <<= 1) {
        int nv = s[t];
        if (t >= o) nv += s[t - o];
        __syncthreads();
        s[t] = nv;
        __syncthreads();
    }
    if (idx < N) {
        int excl = g_bbase[blockIdx.x] + s[t] - v;
        g_off[idx] = excl;
        g_cur[idx] = excl;
    }
}

__global__ void place_kernel(int E)
{
    int i = blockIdx.x * blockDim.x + threadIdx.x;
    if (i >= E) return;
    int d = g_dst[i];
    int p = atomicAdd(&g_cur[d], 1);
    g_epack[p] = make_int2(g_src[i], i);
}

// ---------------- fp16 helpers ----------------
__device__ __forceinline__ uint32_t pack_h2_hi(float a, float b)
{
    __half ha = __float2half_rn(a), hb = __float2half_rn(b);
    return ((uint32_t)__half_as_ushort(hb) << 16) | __half_as_ushort(ha);
}
__device__ __forceinline__ uint32_t pack_h2_lo(float a, float b)
{
    __half ha = __float2half_rn(a), hb = __float2half_rn(b);
    __half la = __float2half_rn(a - __half2float(ha));
    __half lb = __float2half_rn(b - __half2float(hb));
    return ((uint32_t)__half_as_ushort(lb) << 16) | __half_as_ushort(la);
}
__device__ __forceinline__ void ldsm_x4(uint32_t* r, const void* p)
{
    uint32_t a = (uint32_t)__cvta_generic_to_shared(p);
    asm volatile("ldmatrix.sync.aligned.m8n8.x4.shared.b16 {%0,%1,%2,%3}, [%4];"
                 : "=r"(r[0]), "=r"(r[1]), "=r"(r[2]), "=r"(r[3]) : "r"(a));
}
__device__ __forceinline__ void ldsm_x4_t(uint32_t* r, const void* p)
{
    uint32_t a = (uint32_t)__cvta_generic_to_shared(p);
    asm volatile("ldmatrix.sync.aligned.m8n8.x4.trans.shared.b16 {%0,%1,%2,%3}, [%4];"
                 : "=r"(r[0]), "=r"(r[1]), "=r"(r[2]), "=r"(r[3]) : "r"(a));
}
__device__ __forceinline__ void mma_f16(float* c, const uint32_t* a, uint32_t b0, uint32_t b1)
{
    asm volatile("mma.sync.aligned.m16n8k16.row.col.f32.f16.f16.f32 "
                 "{%0,%1,%2,%3}, {%4,%5,%6,%7}, {%8,%9}, {%0,%1,%2,%3};"
                 : "+f"(c[0]), "+f"(c[1]), "+f"(c[2]), "+f"(c[3])
                 : "r"(a[0]), "r"(a[1]), "r"(a[2]), "r"(a[3]), "r"(b0), "r"(b1));
}
__device__ __forceinline__ void cp16(uint32_t dst, const void* src)
{
    asm volatile("cp.async.cg.shared.global [%0], [%1], 16;" :: "r"(dst), "l"(src) : "memory");
}
__device__ __forceinline__ void cp_commit_wait()
{
    asm volatile("cp.async.commit_group;\ncp.async.wait_group 0;" ::: "memory");
}

// ---------------- edge-feature GEMM (both convs): ef[p] = eattr[eid(p)]@We + be ----------------
#define EG_SMEM (2 * PLANE_B + 4 * (16 * LDP * 2) + 1024)

__global__ __launch_bounds__(256, 2)
void edgegemm_kernel(const float* __restrict__ eattr,
                     const float* __restrict__ We1, const float* __restrict__ be1,
                     const float* __restrict__ We2, const float* __restrict__ be2,
                     int E)
{
    extern __shared__ char sm[];
    __half* Ah  = (__half*)sm;                 // [128][LDP], cols 0..15 used
    __half* Al  = Ah + 128 * LDP;
    __half* W1h = Al + 128 * LDP;              // [16][LDP]
    __half* W1l = W1h + 16 * LDP;
    __half* W2h = W1l + 16 * LDP;
    __half* W2l = W2h + 16 * LDP;
    float* sb1 = (float*)(W2l + 16 * LDP);
    float* sb2 = sb1 + 128;

    const int tid = threadIdx.x;
    const int warp = tid >> 5, lane = tid & 31;
    const int p0 = blockIdx.x * 128;

    for (int i = tid; i < 2 * 2048; i += 256) {
        int conv = i >> 11, e = i & 2047;
        int k = e >> 7, n = e & 127;
        const float* W = conv ? We2 : We1;
        float v = __ldg(W + e);
        __half h = __float2half_rn(v);
        __half l = __float2half_rn(v - __half2float(h));
        (conv ? W2h : W1h)[k * LDP + n] = h;
        (conv ? W2l : W1l)[k * LDP + n] = l;
    }
    if (tid < 128) sb1[tid] = __ldg(be1 + tid);
    else           sb2[tid - 128] = __ldg(be2 + tid - 128);

    {
        int rowp = tid >> 1;
        int hoff = (tid & 1) * 8;
        int p = p0 + rowp;
        float4 v0 = make_float4(0.f, 0.f, 0.f, 0.f), v1 = v0;
        if (p < E) {
            int eid = __ldg(&g_epack[p]).y;
            const float4* ea = (const float4*)eattr + (size_t)eid * 4 + (tid & 1) * 2;
            v0 = __ldg(ea);
            v1 = __ldg(ea + 1);
        }
        *(uint2*)(Ah + rowp * LDP + hoff)     = make_uint2(pack_h2_hi(v0.x, v0.y), pack_h2_hi(v0.z, v0.w));
        *(uint2*)(Ah + rowp * LDP + hoff + 4) = make_uint2(pack_h2_hi(v1.x, v1.y), pack_h2_hi(v1.z, v1.w));
        *(uint2*)(Al + rowp * LDP + hoff)     = make_uint2(pack_h2_lo(v0.x, v0.y), pack_h2_lo(v0.z, v0.w));
        *(uint2*)(Al + rowp * LDP + hoff + 4) = make_uint2(pack_h2_lo(v1.x, v1.y), pack_h2_lo(v1.z, v1.w));
    }
    __syncthreads();

    const int wr0 = warp * 16;
    const int arow = wr0 + (lane & 15);
    const int aoff = (lane >> 4) << 3;

    uint32_t ah[4], al[4];
    ldsm_x4(ah, Ah + arow * LDP + aoff);
    ldsm_x4(al, Al + arow * LDP + aoff);

    const int brow = (lane & 15);
    const int cb = (lane & 3) * 2;
    const int r0 = p0 + wr0 + (lane >> 2);

#pragma unroll
    for (int conv = 0; conv < 2; conv++) {
        const __half* Wh = conv ? W2h : W1h;
        const __half* Wl = conv ? W2l : W1l;
        const float* sb = conv ? sb2 : sb1;
        __half* efo = g_ef + (size_t)conv * EMAX * CH;
#pragma unroll
        for (int nh = 0; nh < 2; nh++) {
            float acc[8][4];
#pragma unroll
            for (int t = 0; t < 8; t++)
#pragma unroll
                for (int j = 0; j < 4; j++) acc[t][j] = 0.f;
#pragma unroll
            for (int ng = 0; ng < 4; ng++) {
                const int n0 = nh * 64 + ng * 16;
                uint32_t bh[4], bl[4];
                ldsm_x4_t(bh, Wh + brow * LDP + n0 + aoff);
                ldsm_x4_t(bl, Wl + brow * LDP + n0 + aoff);
                mma_f16(acc[ng * 2],     ah, bh[0], bh[1]);
                mma_f16(acc[ng * 2],     al, bh[0], bh[1]);
                mma_f16(acc[ng * 2],     ah, bl[0], bl[1]);
                mma_f16(acc[ng * 2 + 1], ah, bh[2], bh[3]);
                mma_f16(acc[ng * 2 + 1], al, bh[2], bh[3]);
                mma_f16(acc[ng * 2 + 1], ah, bl[2], bl[3]);
            }
#pragma unroll
            for (int t = 0; t < 8; t++) {
                const int n = nh * 64 + t * 8 + cb;
                const float b0 = sb[n], b1 = sb[n + 1];
                if (r0 < E)
                    *(uint32_t*)(efo + (size_t)r0 * CH + n) =
                        pack_h2_hi(acc[t][0] + b0, acc[t][1] + b1);
                if (r0 + 8 < E)
                    *(uint32_t*)(efo + (size_t)(r0 + 8) * CH + n) =
                        pack_h2_hi(acc[t][2] + b0, acc[t][3] + b1);
            }
        }
    }
}

// ---------------- CSR aggregation (fp16 h planes) ----------------
// z[n] = (1+eps)*(hh[n]+hl[n]) + sum_in relu(hh[src] + ef[p]); one warp per node
__global__ __launch_bounds__(256)
void aggregate_kernel(const __half* __restrict__ hh, const __half* __restrict__ hl,
                      const __half* __restrict__ ef, const float* __restrict__ epsp,
                      float* __restrict__ z, int N)
{
    const float epc = 1.0f + __ldg(epsp);
    const int tid = threadIdx.x;
    const int lane = tid & 31;
    int gw = (blockIdx.x * 256 + tid) >> 5;
    int nw = (gridDim.x * 256) >> 5;

    for (int n = gw; n < N; n += nw) {
        uint2 uh = __ldg((const uint2*)(hh + (size_t)n * CH) + lane);
        uint2 ul = __ldg((const uint2*)(hl + (size_t)n * CH) + lane);
        float2 h01 = __half22float2(*(__half2*)&uh.x);
        float2 h23 = __half22float2(*(__half2*)&uh.y);
        float2 l01 = __half22float2(*(__half2*)&ul.x);
        float2 l23 = __half22float2(*(__half2*)&ul.y);
        float4 acc;
        acc.x = epc * (h01.x + l01.x);
        acc.y = epc * (h01.y + l01.y);
        acc.z = epc * (h23.x + l23.x);
        acc.w = epc * (h23.y + l23.y);

        const int p0 = __ldg(&g_off[n]);
        const int p1 = __ldg(&g_off[n + 1]);

        uint2 su, eu;
        if (p0 < p1) {
            int s = __ldg(&g_epack[p0]).x;
            su = __ldg((const uint2*)(hh + (size_t)s * CH) + lane);
            eu = __ldg((const uint2*)(ef + (size_t)p0 * CH) + lane);
        }
        for (int p = p0; p < p1; ++p) {
            uint2 csu = su, ceu = eu;
            if (p + 1 < p1) {
                int s = __ldg(&g_epack[p + 1]).x;
                su = __ldg((const uint2*)(hh + (size_t)s * CH) + lane);
                eu = __ldg((const uint2*)(ef + (size_t)(p + 1) * CH) + lane);
            }
            float2 s01 = __half22float2(*(__half2*)&csu.x);
            float2 s23 = __half22float2(*(__half2*)&csu.y);
            float2 f01 = __half22float2(*(__half2*)&ceu.x);
            float2 f23 = __half22float2(*(__half2*)&ceu.y);
            acc.x += fmaxf(s01.x + f01.x, 0.f);
            acc.y += fmaxf(s01.y + f01.y, 0.f);
            acc.z += fmaxf(s23.x + f23.x, 0.f);
            acc.w += fmaxf(s23.y + f23.y, 0.f);
        }
        *(float4*)(z + (size_t)n * CH + lane * 4) = acc;
    }
}

// stage A tile (fp32 source) into fp16 hi/lo planes [r][k] LDP pitch
__device__ __forceinline__ void stage_a_f16(const float* __restrict__ A,
                                            __half* Ah, __half* Al,
                                            int tid, int row0, int M)
{
#pragma unroll
    for (int i = 0; i < 16; i++) {
        int idx = tid + i * 256;
        int r = idx >> 5, c4 = idx & 31;
        int g = row0 + r;
        float4 v = make_float4(0.f, 0.f, 0.f, 0.f);
        if (g < M) v = __ldg((const float4*)(A + (size_t)g * CH) + c4);
        *(uint2*)(Ah + r * LDP + c4 * 4) = make_uint2(pack_h2_hi(v.x, v.y), pack_h2_hi(v.z, v.w));
        *(uint2*)(Al + r * LDP + c4 * 4) = make_uint2(pack_h2_lo(v.x, v.y), pack_h2_lo(v.z, v.w));
    }
}

// 2-term fp16 pass, warp tile 32 rows x 64 cols
__device__ __forceinline__ void mma_pass_f16(const __half* Ah, const __half* Al,
                                             const __half* Bh,
                                             int lane, int wr0, int wc0, float acc[2][8][4])
{
#pragma unroll
    for (int rg = 0; rg < 2; rg++)
#pragma unroll
        for (int t = 0; t < 8; t++)
#pragma unroll
            for (int j = 0; j < 4; j++) acc[rg][t][j] = 0.f;

    const int arow = wr0 + (lane & 15);
    const int aoff = (lane >> 4) << 3;

#pragma unroll
    for (int kc = 0; kc < 8; kc++) {
        const int kb = kc * 16;
        uint32_t ah0[4], ah1[4], al0[4], al1[4];
        ldsm_x4(ah0, Ah + (size_t)arow * LDP + kb + aoff);
        ldsm_x4(ah1, Ah + (size_t)(arow + 16) * LDP + kb + aoff);
        ldsm_x4(al0, Al + (size_t)arow * LDP + kb + aoff);
        ldsm_x4(al1, Al + (size_t)(arow + 16) * LDP + kb + aoff);
        const int brow = kb + (lane & 15);
#pragma unroll
        for (int ng = 0; ng < 4; ng++) {
            uint32_t b[4];
            ldsm_x4_t(b, Bh + (size_t)brow * LDP + wc0 + ng * 16 + aoff);
            mma_f16(acc[0][ng * 2],     ah0, b[0], b[1]);
            mma_f16(acc[0][ng * 2],     al0, b[0], b[1]);
            mma_f16(acc[0][ng * 2 + 1], ah0, b[2], b[3]);
            mma_f16(acc[0][ng * 2 + 1], al0, b[2], b[3]);
            mma_f16(acc[1][ng * 2],     ah1, b[0], b[1]);
            mma_f16(acc[1][ng * 2],     al1, b[0], b[1]);
            mma_f16(acc[1][ng * 2 + 1], ah1, b[2], b[3]);
            mma_f16(acc[1][ng * 2 + 1], al1, b[2], b[3]);
        }
    }
}

// ---------------- encoder GEMM: h16 = relu(A @ W + b), split fp16 output ----------------
#define G1_SMEM (3 * PLANE_B + 512)

__global__ __launch_bounds__(256)
void gemm_tc(const float* __restrict__ A, const float4* __restrict__ WhP,
             const float* __restrict__ bias,
             __half* __restrict__ oh, __half* __restrict__ ol, int M)
{
    extern __shared__ char sm[];
    __half* Ah = (__half*)sm;
    __half* Al = Ah + 128 * LDP;
    __half* Wh = Al + 128 * LDP;
    float* sbias = (float*)(sm + 3 * PLANE_B);
    uint32_t sbW = (uint32_t)__cvta_generic_to_shared(Wh);

    const int tid = threadIdx.x;
    const int warp = tid >> 5, lane = tid & 31;
    const int row0 = blockIdx.x * 128;

#pragma unroll
    for (int i = 0; i < 9; i++) {
        int j = tid + i * 256;
        if (j < PLANE_F4) cp16(sbW + j * 16, WhP + j);
    }
    if (tid < 128) sbias[tid] = __ldg(bias + tid);

    stage_a_f16(A, Ah, Al, tid, row0, M);
    cp_commit_wait();
    __syncthreads();

    const int wr0 = (warp >> 1) * 32;
    const int wc0 = (warp & 1) * 64;

    float acc[2][8][4];
    mma_pass_f16(Ah, Al, Wh, lane, wr0, wc0, acc);

    const int cb = (lane & 3) * 2;
#pragma unroll
    for (int rg = 0; rg < 2; rg++) {
        const int r = row0 + wr0 + rg * 16 + (lane >> 2);
#pragma unroll
        for (int t = 0; t < 8; t++) {
            const int n = wc0 + t * 8 + cb;
            const float b0 = sbias[n], b1 = sbias[n + 1];
            float z0 = fmaxf(acc[rg][t][0] + b0, 0.f);
            float z1 = fmaxf(acc[rg][t][1] + b1, 0.f);
            float z2 = fmaxf(acc[rg][t][2] + b0, 0.f);
            float z3 = fmaxf(acc[rg][t][3] + b1, 0.f);
            if (r < M) {
                *(uint32_t*)(oh + (size_t)r * CH + n) = pack_h2_hi(z0, z1);
                *(uint32_t*)(ol + (size_t)r * CH + n) = pack_h2_lo(z0, z1);
            }
            if (r + 8 < M) {
                *(uint32_t*)(oh + (size_t)(r + 8) * CH + n) = pack_h2_hi(z2, z3);
                *(uint32_t*)(ol + (size_t)(r + 8) * CH + n) = pack_h2_lo(z2, z3);
            }
        }
    }
}

// ---------------- fused 2-layer MLP, 3 smem planes (W reloaded between layers) ----------------
// OUT16: write split fp16 h planes; else fp32 out.
#define G2_SMEM (3 * PLANE_B + 1024)

template <bool OUT16>
__global__ __launch_bounds__(256, 2)
void gemm2_tc(const float* __restrict__ A,
              const float4* __restrict__ W1P, const float4* __restrict__ W2P,
              const float* __restrict__ b1, const float* __restrict__ b2,
              float* __restrict__ out, __half* __restrict__ oh, __half* __restrict__ ol,
              int M)
{
    extern __shared__ char sm[];
    __half* Ah = (__half*)sm;        // A tile, reused as Z tile
    __half* Al = Ah + 128 * LDP;
    __half* Wp = Al + 128 * LDP;     // W1 then W2
    float* sb1 = (float*)(sm + 3 * PLANE_B);
    float* sb2 = sb1 + 128;
    uint32_t sbW = (uint32_t)__cvta_generic_to_shared(Wp);

    const int tid = threadIdx.x;
    const int warp = tid >> 5, lane = tid & 31;
    const int row0 = blockIdx.x * 128;

#pragma unroll
    for (int i = 0; i < 9; i++) {
        int j = tid + i * 256;
        if (j < PLANE_F4) cp16(sbW + j * 16, W1P + j);
    }
    if (tid < 128) sb1[tid] = __ldg(b1 + tid);
    else           sb2[tid - 128] = __ldg(b2 + tid - 128);

    stage_a_f16(A, Ah, Al, tid, row0, M);
    cp_commit_wait();
    __syncthreads();

    const int wr0 = (warp >> 1) * 32;
    const int wc0 = (warp & 1) * 64;

    // ---- layer 1 ----
    float acc[2][8][4];
    mma_pass_f16(Ah, Al, Wp, lane, wr0, wc0, acc);
    __syncthreads();   // all warps done reading A planes AND W1

    // reload W plane with W2 while writing z into A planes
#pragma unroll
    for (int i = 0; i < 9; i++) {
        int j = tid + i * 256;
        if (j < PLANE_F4) cp16(sbW + j * 16, W2P + j);
    }
    {
        const int cb = (lane & 3) * 2;
#pragma unroll
        for (int rg = 0; rg < 2; rg++) {
            const int rl = wr0 + rg * 16 + (lane >> 2);
#pragma unroll
            for (int t = 0; t < 8; t++) {
                const int n = wc0 + t * 8 + cb;
                const float b0 = sb1[n], b1v = sb1[n + 1];
                float z0 = fmaxf(acc[rg][t][0] + b0, 0.f);
                float z1 = fmaxf(acc[rg][t][1] + b1v, 0.f);
                float z2 = fmaxf(acc[rg][t][2] + b0, 0.f);
                float z3 = fmaxf(acc[rg][t][3] + b1v, 0.f);
                *(uint32_t*)(Ah + (size_t)rl * LDP + n)       = pack_h2_hi(z0, z1);
                *(uint32_t*)(Al + (size_t)rl * LDP + n)       = pack_h2_lo(z0, z1);
                *(uint32_t*)(Ah + (size_t)(rl + 8) * LDP + n) = pack_h2_hi(z2, z3);
                *(uint32_t*)(Al + (size_t)(rl + 8) * LDP + n) = pack_h2_lo(z2, z3);
            }
        }
    }
    cp_commit_wait();
    __syncthreads();

    // ---- layer 2 ----
    mma_pass_f16(Ah, Al, Wp, lane, wr0, wc0, acc);

    const int cb = (lane & 3) * 2;
#pragma unroll
    for (int rg = 0; rg < 2; rg++) {
        const int r = row0 + wr0 + rg * 16 + (lane >> 2);
#pragma unroll
        for (int t = 0; t < 8; t++) {
            const int n = wc0 + t * 8 + cb;
            const float b0 = sb2[n], b1v = sb2[n + 1];
            float z0 = fmaxf(acc[rg][t][0] + b0, 0.f);
            float z1 = fmaxf(acc[rg][t][1] + b1v, 0.f);
            float z2 = fmaxf(acc[rg][t][2] + b0, 0.f);
            float z3 = fmaxf(acc[rg][t][3] + b1v, 0.f);
            if (OUT16) {
                if (r < M) {
                    *(uint32_t*)(oh + (size_t)r * CH + n) = pack_h2_hi(z0, z1);
                    *(uint32_t*)(ol + (size_t)r * CH + n) = pack_h2_lo(z0, z1);
                }
                if (r + 8 < M) {
                    *(uint32_t*)(oh + (size_t)(r + 8) * CH + n) = pack_h2_hi(z2, z3);
                    *(uint32_t*)(ol + (size_t)(r + 8) * CH + n) = pack_h2_lo(z2, z3);
                }
            } else {
                if (r < M) {
                    float2 o = make_float2(z0, z1);
                    *(float2*)(out + (size_t)r * CH + n) = o;
                }
                if (r + 8 < M) {
                    float2 o = make_float2(z2, z3);
                    *(float2*)(out + (size_t)(r + 8) * CH + n) = o;
                }
            }
        }
    }
}

// ---------------- launch ----------------
extern "C" void kernel_launch(void* const* d_in, const int* in_sizes, int n_in,
                              void* d_out, int out_size)
{
    const float* x     = (const float*)d_in[0];
    const void*  eidx  = d_in[1];
    const float* eattr = (const float*)d_in[2];
    const float* W_enc = (const float*)d_in[3];
    const float* b_enc = (const float*)d_in[4];
    const float* We1   = (const float*)d_in[5];
    const float* be1   = (const float*)d_in[6];
    const float* W11   = (const float*)d_in[7];
    const float* b11   = (const float*)d_in[8];
    const float* W12   = (const float*)d_in[9];
    const float* b12   = (const float*)d_in[10];
    const float* eps1  = (const float*)d_in[11];
    const float* We2   = (const float*)d_in[12];
    const float* be2   = (const float*)d_in[13];
    const float* W21   = (const float*)d_in[14];
    const float* b21   = (const float*)d_in[15];
    const float* W22   = (const float*)d_in[16];
    const float* b22   = (const float*)d_in[17];
    const float* eps2  = (const float*)d_in[18];

    const int N = in_sizes[0] / CH;
    const int E = in_sizes[2] / 16;
    float* out = (float*)d_out;

    float* aggP;
    float4* wpl;
    __half *efP, *hhP, *hlP;
    cudaGetSymbolAddress((void**)&aggP, g_agg);
    cudaGetSymbolAddress((void**)&wpl, g_wplanes);
    cudaGetSymbolAddress((void**)&efP, g_ef);
    cudaGetSymbolAddress((void**)&hhP, g_hh);
    cudaGetSymbolAddress((void**)&hlP, g_hl);

    cudaFuncSetAttribute((const void*)gemm_tc,
                         cudaFuncAttributeMaxDynamicSharedMemorySize, G1_SMEM);
    cudaFuncSetAttribute((const void*)gemm2_tc<true>,
                         cudaFuncAttributeMaxDynamicSharedMemorySize, G2_SMEM);
    cudaFuncSetAttribute((const void*)gemm2_tc<false>,
                         cudaFuncAttributeMaxDynamicSharedMemorySize, G2_SMEM);
    cudaFuncSetAttribute((const void*)edgegemm_kernel,
                         cudaFuncAttributeMaxDynamicSharedMemorySize, EG_SMEM);

    const int nb = (N + 1023) / 1024;
    const int gb = (N + 127) / 128;

    detect_idx_kernel<<<1, 256>>>((const unsigned*)eidx, 2 * E);                    // 1
    prep_weights<<<(5 * 128 * LDP + 255) / 256, 256>>>(W_enc, W11, W12, W21, W22);  // 2
    zero_counts_kernel<<<nb, 1024>>>(N);                                            // 3
    gemm_tc<<<gb, 256, G1_SMEM>>>(x, wpl, b_enc, hhP, hlP, N);                      // 4 (profiled)
    convert_hist_kernel<<<(E + 255) / 256, 256>>>(eidx, E);
    scan1_kernel<<<nb, 1024>>>(N);
    scan2_kernel<<<1, 256>>>(nb, N, E);
    scan3_kernel<<<nb, 1024>>>(N);
    place_kernel<<<(E + 255) / 256, 256>>>(E);
    edgegemm_kernel<<<(E + 127) / 128, 256, EG_SMEM>>>(eattr, We1, be1, We2, be2, E);

    // ---- conv1 ----
    aggregate_kernel<<<2368, 256>>>(hhP, hlP, efP, eps1, aggP, N);
    gemm2_tc<true><<<gb, 256, G2_SMEM>>>(aggP, wpl + 1 * PLANE_F4, wpl + 2 * PLANE_F4,
                                         b11, b12, nullptr, hhP, hlP, N);

    // ---- conv2 ----
    aggregate_kernel<<<2368, 256>>>(hhP, hlP, efP + (size_t)EMAX * CH, eps2, aggP, N);
    gemm2_tc<false><<<gb, 256, G2_SMEM>>>(aggP, wpl + 3 * PLANE_F4, wpl + 4 * PLANE_F4,
                                          b21, b22, out, nullptr, nullptr, N);
}